// round 14
// baseline (speedup 1.0000x reference)
#include <cuda_runtime.h>
#include <cuda_bf16.h>
#include <stdint.h>
#include <math.h>

#define S_LEN   50
#define T_STEPS 39
#define BATCH   32
#define EMB     256
#define HID     512
#define G4      2048
#define VOCAB   32000
#define NBLK    128
#define NGRP    64
#define MPAD    1280
#define XROWS   2944
#define DECOFF  1664

// ---------------- scratch (device globals) ----------------------------------
__device__ float s2s_x_all [XROWS * EMB];
__device__ float s2s_xw_all[XROWS * G4];
__device__ unsigned s2s_barA, s2s_barB;
__device__ __nv_bfloat16 s2s_h0hi [4 * BATCH * HID];
__device__ __nv_bfloat16 s2s_h0lo [4 * BATCH * HID];
__device__ __nv_bfloat16 s2s_acthi[4 * BATCH * 1024];
__device__ __nv_bfloat16 s2s_actlo[4 * BATCH * 1024];
__device__ __nv_bfloat16 s2s_dy1hi[MPAD * HID];
__device__ __nv_bfloat16 s2s_dy1lo[MPAD * HID];
__device__ __nv_bfloat16 s2s_wvhi [VOCAB * HID];
__device__ __nv_bfloat16 s2s_wvlo [VOCAB * HID];

// ---------------- helpers ----------------------------------------------------
__device__ __forceinline__ float s2s_sigm(float x) { return 1.0f / (1.0f + expf(-x)); }
__device__ __forceinline__ void s2s_split(float v, __nv_bfloat16* hi, __nv_bfloat16* lo) {
    __nv_bfloat16 h = __float2bfloat16(v);
    *hi = h;
    *lo = __float2bfloat16(v - __bfloat162float(h));
}
__device__ __forceinline__ uint32_t s2s_ld2(const __nv_bfloat16* p) {
    return *reinterpret_cast<const uint32_t*>(p);
}
__device__ __forceinline__ void s2s_mma(float* d, const uint32_t* a, const uint32_t* b) {
    asm volatile(
        "mma.sync.aligned.m16n8k16.row.col.f32.bf16.bf16.f32 "
        "{%0,%1,%2,%3}, {%4,%5,%6,%7}, {%8,%9}, {%0,%1,%2,%3};\n"
        : "+f"(d[0]), "+f"(d[1]), "+f"(d[2]), "+f"(d[3])
        : "r"(a[0]), "r"(a[1]), "r"(a[2]), "r"(a[3]), "r"(b[0]), "r"(b[1]));
}
__device__ __forceinline__ uint32_t s2s_smem_u32(const void* p) {
    uint32_t a;
    asm("{ .reg .u64 t; cvta.to.shared.u64 t, %1; cvt.u32.u64 %0, t; }" : "=r"(a) : "l"(p));
    return a;
}
__device__ __forceinline__ void s2s_ldsm4(uint32_t* r, uint32_t addr) {
    asm volatile("ldmatrix.sync.aligned.m8n8.x4.shared.b16 {%0,%1,%2,%3}, [%4];"
                 : "=r"(r[0]), "=r"(r[1]), "=r"(r[2]), "=r"(r[3]) : "r"(addr));
}
__device__ __forceinline__ void s2s_cpasync(uint32_t dst, const void* src) {
    asm volatile("cp.async.cg.shared.global [%0], [%1], 16;" :: "r"(dst), "l"(src) : "memory");
}
#define CP_COMMIT() asm volatile("cp.async.commit_group;" ::: "memory")
#define CP_WAIT1()  asm volatile("cp.async.wait_group 1;" ::: "memory")
#define CP_WAIT0()  asm volatile("cp.async.wait_group 0;" ::: "memory")
__device__ __forceinline__ void s2s_st16(__nv_bfloat16* p, __nv_bfloat16 v) {
    unsigned short u = *reinterpret_cast<unsigned short*>(&v);
    asm volatile("st.global.cg.u16 [%0], %1;" :: "l"(p), "h"(u) : "memory");
}

// ---------------- init / embed / split ---------------------------------------
__global__ void s2s_init_kernel(float* __restrict__ out) {
    int i = blockIdx.x * 256 + threadIdx.x;
    if (i < BATCH * VOCAB) out[i] = 0.0f;
    if (i < 4 * BATCH * HID)  { s2s_h0hi[i] = __nv_bfloat16(0.f); s2s_h0lo[i] = __nv_bfloat16(0.f); }
    if (i < 4 * BATCH * 1024) { s2s_acthi[i] = __nv_bfloat16(0.f); s2s_actlo[i] = __nv_bfloat16(0.f); }
    if (i < MPAD * HID)       { s2s_dy1hi[i] = __nv_bfloat16(0.f); s2s_dy1lo[i] = __nv_bfloat16(0.f); }
    if (i == 0) { s2s_barA = 0u; s2s_barB = 0u; }
}

__global__ void s2s_embed_all(const int* __restrict__ src, const int* __restrict__ trg,
                              const float* __restrict__ eemb, const float* __restrict__ demb) {
    int i = blockIdx.x * 256 + threadIdx.x;
    if (i >= (S_LEN + T_STEPS) * BATCH * EMB) return;
    int r = i >> 8, e = i & 255;
    if (r < S_LEN * BATCH)
        s2s_x_all[r * EMB + e] = eemb[(size_t)src[r] * EMB + e];
    else {
        int rd = r - S_LEN * BATCH;
        s2s_x_all[(DECOFF + rd) * EMB + e] = demb[(size_t)trg[rd] * EMB + e];
    }
}

__global__ void s2s_split_mat(const float* __restrict__ src, __nv_bfloat16* __restrict__ hi,
                              __nv_bfloat16* __restrict__ lo, int n) {
    int i = blockIdx.x * 256 + threadIdx.x;
    if (i >= n) return;
    float v = src[i];
    __nv_bfloat16 h = __float2bfloat16(v);
    hi[i] = h;
    lo[i] = __float2bfloat16(v - __bfloat162float(h));
}

// ---- combined x-projection (unchanged, passing) ------------------------------
#define GBM 128
#define GBN 64
#define GBK 32
#define GPAD 40

__global__ __launch_bounds__(256)
void s2s_xproj(const float* __restrict__ We, const float* __restrict__ be,
               const float* __restrict__ Wd, const float* __restrict__ bd) {
    __shared__ __nv_bfloat16 shA[2][GBM][GPAD];
    __shared__ __nv_bfloat16 shB[2][GBN][GPAD];
    const int tid = threadIdx.x;
    const int warp = tid >> 5, lane = tid & 31;
    const int wm = warp >> 1, wn = warp & 1;
    const int g = lane >> 2, tq = lane & 3;
    const int bm = blockIdx.x * GBM, bn = blockIdx.y * GBN;
    const int tr = tid >> 3, c4 = (tid & 7) * 4;

    const bool enc = (bm < DECOFF);
    const float* Bw   = enc ? We : Wd;
    const float* bias = enc ? be : bd;
    const int Ml      = enc ? (S_LEN * BATCH) : (DECOFF + T_STEPS * BATCH);
    const float* A = s2s_x_all;
    float* C = s2s_xw_all;
    const int K = EMB;

    float acc[2][4][4];
#pragma unroll
    for (int i = 0; i < 2; i++)
#pragma unroll
        for (int j = 0; j < 4; j++)
#pragma unroll
            for (int k = 0; k < 4; k++) acc[i][j][k] = 0.0f;

    float4 ra[4], rb[2];
#pragma unroll
    for (int q = 0; q < 4; q++) {
        int row = bm + q * 32 + tr;
        ra[q] = (row < Ml) ? *(const float4*)&A[(size_t)row * K + c4]
                           : make_float4(0.f, 0.f, 0.f, 0.f);
    }
#pragma unroll
    for (int q = 0; q < 2; q++)
        rb[q] = *(const float4*)&Bw[(size_t)(bn + q * 32 + tr) * K + c4];

    for (int ch = 0; ch < K / GBK; ch++) {
        __syncthreads();
#pragma unroll
        for (int q = 0; q < 4; q++) {
            const float* pv = (const float*)&ra[q];
#pragma unroll
            for (int j = 0; j < 4; j++)
                s2s_split(pv[j], &shA[0][q * 32 + tr][c4 + j], &shA[1][q * 32 + tr][c4 + j]);
        }
#pragma unroll
        for (int q = 0; q < 2; q++) {
            const float* pv = (const float*)&rb[q];
#pragma unroll
            for (int j = 0; j < 4; j++)
                s2s_split(pv[j], &shB[0][q * 32 + tr][c4 + j], &shB[1][q * 32 + tr][c4 + j]);
        }
        __syncthreads();
        if (ch + 1 < K / GBK) {
            int k0 = (ch + 1) * GBK;
#pragma unroll
            for (int q = 0; q < 4; q++) {
                int row = bm + q * 32 + tr;
                ra[q] = (row < Ml) ? *(const float4*)&A[(size_t)row * K + k0 + c4]
                                   : make_float4(0.f, 0.f, 0.f, 0.f);
            }
#pragma unroll
            for (int q = 0; q < 2; q++)
                rb[q] = *(const float4*)&Bw[(size_t)(bn + q * 32 + tr) * K + k0 + c4];
        }
#pragma unroll
        for (int kk = 0; kk < 2; kk++) {
            const int ko = kk * 16;
            uint32_t ah[2][4], al[2][4], bh[4][2], bl[4][2];
#pragma unroll
            for (int mt = 0; mt < 2; mt++) {
                int r0 = wm * 32 + mt * 16;
                ah[mt][0] = s2s_ld2(&shA[0][r0 + g][ko + 2 * tq]);
                ah[mt][1] = s2s_ld2(&shA[0][r0 + g + 8][ko + 2 * tq]);
                ah[mt][2] = s2s_ld2(&shA[0][r0 + g][ko + 2 * tq + 8]);
                ah[mt][3] = s2s_ld2(&shA[0][r0 + g + 8][ko + 2 * tq + 8]);
                al[mt][0] = s2s_ld2(&shA[1][r0 + g][ko + 2 * tq]);
                al[mt][1] = s2s_ld2(&shA[1][r0 + g + 8][ko + 2 * tq]);
                al[mt][2] = s2s_ld2(&shA[1][r0 + g][ko + 2 * tq + 8]);
                al[mt][3] = s2s_ld2(&shA[1][r0 + g + 8][ko + 2 * tq + 8]);
            }
#pragma unroll
            for (int nt = 0; nt < 4; nt++) {
                int rn = wn * 32 + nt * 8 + g;
                bh[nt][0] = s2s_ld2(&shB[0][rn][ko + 2 * tq]);
                bh[nt][1] = s2s_ld2(&shB[0][rn][ko + 2 * tq + 8]);
                bl[nt][0] = s2s_ld2(&shB[1][rn][ko + 2 * tq]);
                bl[nt][1] = s2s_ld2(&shB[1][rn][ko + 2 * tq + 8]);
            }
#pragma unroll
            for (int mt = 0; mt < 2; mt++)
#pragma unroll
                for (int nt = 0; nt < 4; nt++) {
                    s2s_mma(acc[mt][nt], ah[mt], bh[nt]);
                    s2s_mma(acc[mt][nt], ah[mt], bl[nt]);
                    s2s_mma(acc[mt][nt], al[mt], bh[nt]);
                }
        }
    }
#pragma unroll
    for (int mt = 0; mt < 2; mt++)
#pragma unroll
        for (int nt = 0; nt < 4; nt++) {
            int col = bn + wn * 32 + nt * 8 + 2 * tq;
            float b0v = bias[col], b1v = bias[col + 1];
            int r0 = bm + wm * 32 + mt * 16 + g;
            if (r0 < Ml) {
                float* p = &C[(size_t)r0 * G4 + col];
                p[0] = acc[mt][nt][0] + b0v;
                p[1] = acc[mt][nt][1] + b1v;
            }
            if (r0 + 8 < Ml) {
                float* p = &C[(size_t)(r0 + 8) * G4 + col];
                p[0] = acc[mt][nt][2] + b0v;
                p[1] = acc[mt][nt][3] + b1v;
            }
        }
}

// ---------------- persistent recurrence: split-K 512 threads (R13, passing) ---
#define WS 1032
#define AS 520
#define SMEM_BYTES 206848
#define ABYTES (AS * 2)
#define WBYTES (WS * 2)

__device__ __forceinline__ void s2s_sweepK(uint32_t aHi, uint32_t aLo,
                                           uint32_t wHi, uint32_t wLo,
                                           int aoff, int boff, int kt0,
                                           float* acc) {
#pragma unroll
    for (int kt2 = 0; kt2 < 8; kt2++) {
        const int k0b = (kt0 + kt2) * 64;
        uint32_t ah0[4], ah1[4], al0[4], al1[4], bh[4], bl[4];
        s2s_ldsm4(ah0, aHi + aoff + k0b);
        s2s_ldsm4(ah1, aHi + aoff + k0b + 32);
        s2s_ldsm4(al0, aLo + aoff + k0b);
        s2s_ldsm4(al1, aLo + aoff + k0b + 32);
        s2s_ldsm4(bh,  wHi + boff + k0b);
        s2s_ldsm4(bl,  wLo + boff + k0b);
        s2s_mma(acc, ah0, bh);
        s2s_mma(acc, ah0, bl);
        s2s_mma(acc, al0, bh);
        s2s_mma(acc, ah1, bh + 2);
        s2s_mma(acc, ah1, bl + 2);
        s2s_mma(acc, al1, bh + 2);
    }
}

__global__ __launch_bounds__(512, 1)
void s2s_lstm_persist(const float* __restrict__ eWhh0, const float* __restrict__ eWih1,
                      const float* __restrict__ eWhh1, const float* __restrict__ eb1,
                      const float* __restrict__ dWhh0, const float* __restrict__ dWih1,
                      const float* __restrict__ dWhh1, const float* __restrict__ db1) {
    extern __shared__ __nv_bfloat16 sm[];
    __nv_bfloat16* whi = sm;
    __nv_bfloat16* wlo = sm + 33024;
    __nv_bfloat16* ahi = sm + 66048;
    __nv_bfloat16* alo = sm + 82688;
    float* shG = (float*)(sm + 99328);
    const uint32_t aHiB = s2s_smem_u32(ahi), aLoB = s2s_smem_u32(alo);
    const uint32_t wHiB = s2s_smem_u32(whi), wLoB = s2s_smem_u32(wlo);

    const int tid = threadIdx.x, warp = tid >> 5, lane = tid & 31;
    const int kh = warp >> 3;
    const int mt = (warp >> 2) & 1, gw = warp & 3;
    const int g = lane >> 2, tq = lane & 3;
    const bool isA = blockIdx.x < NGRP;
    const int u0 = (isA ? blockIdx.x : blockIdx.x - NGRP) * 8;
    const int lrow = (tid & 255) >> 3, c4 = (tid & 7) * 4;
    const int WR = (lrow >> 3) * HID + u0 + (lrow & 7);
    const int eb = (tid & 255) >> 3, eu = tid & 7;
    const int U = u0 + eu;
    const int aoff = (mt * 16 + (lane & 15)) * ABYTES + ((lane >> 4) << 4);
    const int boff = (gw * 8 + (lane & 7)) * WBYTES + ((lane >> 3) << 4);
    const bool low = (tid < 256);

    float creg = 0.0f;
    unsigned iter = 0;

    for (int phase = 0; phase < 2; phase++) {
        const float* Whh0 = phase ? dWhh0 : eWhh0;
        const float* Wih1 = phase ? dWih1 : eWih1;
        const float* Whh1 = phase ? dWhh1 : eWhh1;
        const float* bb1  = phase ? db1  : eb1;
        const float* xw   = s2s_xw_all + (phase ? (size_t)DECOFF * G4 : 0);
        const int steps   = phase ? T_STEPS : S_LEN;
        const int gbase   = phase ? S_LEN : 0;

        float bi1 = 0.f, bf1 = 0.f, bc1 = 0.f, bo1 = 0.f;
        if (!isA && low) {
            bi1 = __ldg(&bb1[U]); bf1 = __ldg(&bb1[HID + U]);
            bc1 = __ldg(&bb1[2 * HID + U]); bo1 = __ldg(&bb1[3 * HID + U]);
        }

        if (low) {
            if (isA) {
                for (int col = c4; col < HID; col += 32) {
                    float4 v = *(const float4*)&Whh0[(size_t)WR * HID + col];
                    const float* pv = (const float*)&v;
#pragma unroll
                    for (int i = 0; i < 4; i++)
                        s2s_split(pv[i], &whi[lrow * WS + col + i], &wlo[lrow * WS + col + i]);
                }
            } else {
                for (int col = c4; col < HID; col += 32) {
                    float4 v = *(const float4*)&Wih1[(size_t)WR * HID + col];
                    const float* pv = (const float*)&v;
#pragma unroll
                    for (int i = 0; i < 4; i++)
                        s2s_split(pv[i], &whi[lrow * WS + col + i], &wlo[lrow * WS + col + i]);
                    float4 v2 = *(const float4*)&Whh1[(size_t)WR * HID + col];
                    const float* pw = (const float*)&v2;
#pragma unroll
                    for (int i = 0; i < 4; i++)
                        s2s_split(pw[i], &whi[lrow * WS + 512 + col + i], &wlo[lrow * WS + 512 + col + i]);
                }
            }
        }
        __syncthreads();

        for (int j = 0; j <= steps; j++) {
            const bool act_me = isA ? (j < steps) : (j >= 1);
            if (act_me) {
                float acc[4] = {0.f, 0.f, 0.f, 0.f};
                if (isA) {
                    const int gs = gbase + j;
                    const int rs = (gs + 3) & 3, ws = gs & 3;
                    const __nv_bfloat16* gHi = s2s_h0hi + (size_t)rs * BATCH * HID;
                    const __nv_bfloat16* gLo = s2s_h0lo + (size_t)rs * BATCH * HID;
#pragma unroll
                    for (int v = 0; v < 4; v++) {
                        int idx = tid + v * 512;
                        int row = idx >> 6, col = (idx & 63) * 8;
                        uint32_t d = (uint32_t)(row * ABYTES + col * 2);
                        s2s_cpasync(aHiB + d, gHi + (size_t)row * HID + col);
                        s2s_cpasync(aLoB + d, gLo + (size_t)row * HID + col);
                    }
                    CP_COMMIT();
                    float xg0 = 0.f, xg1 = 0.f, xg2 = 0.f, xg3 = 0.f;
                    if (low) {
                        const float* xwt = xw + (size_t)j * BATCH * G4 + (size_t)eb * G4;
                        xg0 = __ldg(&xwt[U]); xg1 = __ldg(&xwt[HID + U]);
                        xg2 = __ldg(&xwt[2 * HID + U]); xg3 = __ldg(&xwt[3 * HID + U]);
                    }
                    CP_WAIT0();
                    __syncthreads();
                    s2s_sweepK(aHiB, aLoB, wHiB, wLoB, aoff, boff, kh * 8, acc);
                    float* sg = shG + kh * 1024 + gw * 256;
                    sg[(mt * 16 + g) * 8 + 2 * tq]         = acc[0];
                    sg[(mt * 16 + g) * 8 + 2 * tq + 1]     = acc[1];
                    sg[(mt * 16 + g + 8) * 8 + 2 * tq]     = acc[2];
                    sg[(mt * 16 + g + 8) * 8 + 2 * tq + 1] = acc[3];
                    __syncthreads();
                    if (low) {
                        const int o = eb * 8 + eu;
                        float gi = shG[o]        + shG[1024 + o] + xg0;
                        float gf = shG[256 + o]  + shG[1280 + o] + xg1;
                        float gc = shG[512 + o]  + shG[1536 + o] + xg2;
                        float go = shG[768 + o]  + shG[1792 + o] + xg3;
                        creg = s2s_sigm(gf) * creg + s2s_sigm(gi) * tanhf(gc);
                        float h = s2s_sigm(go) * tanhf(creg);
                        __nv_bfloat16 hh, hl;
                        s2s_split(h, &hh, &hl);
                        const size_t o1 = (size_t)ws * BATCH * HID + eb * HID + U;
                        const size_t o2 = (size_t)ws * BATCH * 1024 + eb * 1024 + U;
                        s2s_st16(&s2s_h0hi[o1], hh);  s2s_st16(&s2s_h0lo[o1], hl);
                        s2s_st16(&s2s_acthi[o2], hh); s2s_st16(&s2s_actlo[o2], hl);
                    }
                } else {
                    const int gs2 = gbase + j - 1;
                    const int sy = gs2 & 3, sh = (gs2 + 3) & 3, ws2 = gs2 & 3;
                    const __nv_bfloat16* yHi = s2s_acthi + (size_t)sy * BATCH * 1024;
                    const __nv_bfloat16* yLo = s2s_actlo + (size_t)sy * BATCH * 1024;
                    const __nv_bfloat16* hHi = s2s_acthi + (size_t)sh * BATCH * 1024;
                    const __nv_bfloat16* hLo = s2s_actlo + (size_t)sh * BATCH * 1024;
#pragma unroll
                    for (int v = 0; v < 4; v++) {
                        int idx = tid + v * 512;
                        int row = idx >> 6, col = (idx & 63) * 8;
                        uint32_t d = (uint32_t)(row * ABYTES + col * 2);
                        s2s_cpasync(aHiB + d, yHi + (size_t)row * 1024 + col);
                        s2s_cpasync(aLoB + d, yLo + (size_t)row * 1024 + col);
                    }
                    CP_COMMIT();
                    uint4 rh[4], rl[4];
#pragma unroll
                    for (int v = 0; v < 4; v++) {
                        int idx = tid + v * 512;
                        int row = idx >> 6, col = (idx & 63) * 8;
                        rh[v] = __ldcg((const uint4*)(hHi + (size_t)row * 1024 + 512 + col));
                        rl[v] = __ldcg((const uint4*)(hLo + (size_t)row * 1024 + 512 + col));
                    }
                    CP_WAIT0();
                    __syncthreads();
                    s2s_sweepK(aHiB, aLoB, wHiB, wLoB, aoff, boff, kh * 8, acc);
                    __syncthreads();
#pragma unroll
                    for (int v = 0; v < 4; v++) {
                        int idx = tid + v * 512;
                        int row = idx >> 6, col = (idx & 63) * 8;
                        uint32_t d = (uint32_t)(row * ABYTES + col * 2);
                        *(uint4*)((char*)ahi + d) = rh[v];
                        *(uint4*)((char*)alo + d) = rl[v];
                    }
                    __syncthreads();
                    s2s_sweepK(aHiB, aLoB, wHiB + 1024, wLoB + 1024, aoff, boff, kh * 8, acc);
                    float* sg = shG + kh * 1024 + gw * 256;
                    sg[(mt * 16 + g) * 8 + 2 * tq]         = acc[0];
                    sg[(mt * 16 + g) * 8 + 2 * tq + 1]     = acc[1];
                    sg[(mt * 16 + g + 8) * 8 + 2 * tq]     = acc[2];
                    sg[(mt * 16 + g + 8) * 8 + 2 * tq + 1] = acc[3];
                    __syncthreads();
                    if (low) {
                        const int o = eb * 8 + eu;
                        float gi = shG[o]       + shG[1024 + o] + bi1;
                        float gf = shG[256 + o] + shG[1280 + o] + bf1;
                        float gc = shG[512 + o] + shG[1536 + o] + bc1;
                        float go = shG[768 + o] + shG[1792 + o] + bo1;
                        creg = s2s_sigm(gf) * creg + s2s_sigm(gi) * tanhf(gc);
                        float h = s2s_sigm(go) * tanhf(creg);
                        __nv_bfloat16 hh, hl;
                        s2s_split(h, &hh, &hl);
                        const size_t o2 = (size_t)ws2 * BATCH * 1024 + eb * 1024 + 512 + U;
                        s2s_st16(&s2s_acthi[o2], hh); s2s_st16(&s2s_actlo[o2], hl);
                        if (phase == 1) {
                            const size_t od = (size_t)(j - 1) * BATCH * HID + eb * HID + U;
                            s2s_dy1hi[od] = hh;
                            s2s_dy1lo[od] = hl;
                        }
                    }
                }
            }
            iter++;
            __syncthreads();
            if (tid == 0) {
                __threadfence();
                unsigned* myB = isA ? &s2s_barA : &s2s_barB;
                atomicAdd(myB, 1u);
                while (*(volatile unsigned*)myB < iter * NGRP) { }
                if (isA) {
                    if (iter > 3)
                        while (*(volatile unsigned*)&s2s_barB < (iter - 3) * NGRP) { }
                } else {
                    while (*(volatile unsigned*)&s2s_barA < iter * NGRP) { }
                }
                __threadfence();
            }
            __syncthreads();
        }
    }
}

// ---------------- vocab projection: K-chunk 64, 2 stages (128 KB smem) -------
#define VTILE  16384
#define VSTAGE 65536
#define VSMEM  131072

__device__ __forceinline__ uint32_t s2s_vswz(int row, int c16) {
    return (uint32_t)(row * 128 + ((c16 ^ (row & 7)) << 4));
}

__global__ __launch_bounds__(256)
void s2s_vgemm(const __nv_bfloat16* __restrict__ Ahi, const __nv_bfloat16* __restrict__ Alo,
               const __nv_bfloat16* __restrict__ Bhi, const __nv_bfloat16* __restrict__ Blo,
               const float* __restrict__ bias, float* __restrict__ C, int Mvalid) {
    extern __shared__ char vsm[];
    const uint32_t sb = s2s_smem_u32(vsm);
    const int tid = threadIdx.x, wid = tid >> 5, lane = tid & 31;
    const int wm = wid >> 2, wn = wid & 3;
    const int g = lane >> 2, tq = lane & 3;
    const int bm = blockIdx.x * 128, bn = blockIdx.y * 128;

    const __nv_bfloat16* srcs[4] = {
        Ahi + (size_t)bm * HID, Alo + (size_t)bm * HID,
        Bhi + (size_t)bn * HID, Blo + (size_t)bn * HID };

    // stage one K-64 chunk: 4 tiles x 128 rows x 64 cols (8 slots of 16B)
    auto prefetch = [&](int ch, int st) {
#pragma unroll
        for (int t = 0; t < 4; t++) {
#pragma unroll
            for (int v = 0; v < 4; v++) {
                int idx = tid + v * 256;
                int row = idx >> 3, c16 = idx & 7;
                const __nv_bfloat16* gp = srcs[t] + (size_t)row * HID + ch * 64 + c16 * 8;
                s2s_cpasync(sb + st * VSTAGE + t * VTILE + s2s_vswz(row, c16), gp);
            }
        }
    };

    float acc[4][4][4];
#pragma unroll
    for (int i = 0; i < 4; i++)
#pragma unroll
        for (int j = 0; j < 4; j++)
#pragma unroll
            for (int k = 0; k < 4; k++) acc[i][j][k] = 0.0f;

    prefetch(0, 0);
    CP_COMMIT();

    for (int ch = 0; ch < 8; ch++) {
        const int st = ch & 1;
        if (ch + 1 < 8) { prefetch(ch + 1, st ^ 1); CP_COMMIT(); }
        if (ch + 1 < 8) { CP_WAIT1(); } else { CP_WAIT0(); }
        __syncthreads();

        const uint32_t base = sb + st * VSTAGE;
#pragma unroll
        for (int kk = 0; kk < 4; kk++) {
            uint32_t ah[4][4], al[4][4], bh2[2][4], bl2[2][4];
            const int arow = wm * 64 + (lane & 15);
            const int ac16 = kk * 2 + (lane >> 4);
#pragma unroll
            for (int mt = 0; mt < 4; mt++) {
                const uint32_t off = s2s_vswz(arow + mt * 16, ac16);
                s2s_ldsm4(ah[mt], base + off);
                s2s_ldsm4(al[mt], base + VTILE + off);
            }
            const int brow = wn * 32 + ((lane >> 4) << 3) + (lane & 7);
            const int bc16 = kk * 2 + ((lane >> 3) & 1);
#pragma unroll
            for (int nt2 = 0; nt2 < 2; nt2++) {
                const uint32_t off = s2s_vswz(brow + nt2 * 16, bc16);
                s2s_ldsm4(bh2[nt2], base + 2 * VTILE + off);
                s2s_ldsm4(bl2[nt2], base + 3 * VTILE + off);
            }
#pragma unroll
            for (int mt = 0; mt < 4; mt++)
#pragma unroll
                for (int nt = 0; nt < 4; nt++) {
                    const uint32_t* bh = &bh2[nt >> 1][(nt & 1) * 2];
                    const uint32_t* bl = &bl2[nt >> 1][(nt & 1) * 2];
                    s2s_mma(acc[mt][nt], ah[mt], bh);
                    s2s_mma(acc[mt][nt], ah[mt], bl);
                    s2s_mma(acc[mt][nt], al[mt], bh);
                }
        }
        __syncthreads();
    }

#pragma unroll
    for (int mt = 0; mt < 4; mt++) {
#pragma unroll
        for (int nt = 0; nt < 4; nt++) {
            const int col = bn + wn * 32 + nt * 8 + 2 * tq;
            const float b0 = bias[col], b1 = bias[col + 1];
            const int r0 = bm + wm * 64 + mt * 16 + g;
            if (r0 < Mvalid) {
                float2 o = { acc[mt][nt][0] + b0, acc[mt][nt][1] + b1 };
                *(float2*)&C[(size_t)(r0 + BATCH) * VOCAB + col] = o;
            }
            if (r0 + 8 < Mvalid) {
                float2 o = { acc[mt][nt][2] + b0, acc[mt][nt][3] + b1 };
                *(float2*)&C[(size_t)(r0 + 8 + BATCH) * VOCAB + col] = o;
            }
        }
    }
}

static inline int s2s_grid(int n) { return (n + 255) / 256; }

extern "C" void kernel_launch(void* const* d_in, const int* in_sizes, int n_in,
                              void* d_out, int out_size) {
    (void)in_sizes; (void)n_in; (void)out_size;
    const int*   src      = (const int*)  d_in[0];
    const int*   trg      = (const int*)  d_in[1];
    const float* enc_emb  = (const float*)d_in[2];
    const float* enc_Wih0 = (const float*)d_in[3];
    const float* enc_Whh0 = (const float*)d_in[4];
    const float* enc_b0   = (const float*)d_in[5];
    const float* enc_Wih1 = (const float*)d_in[6];
    const float* enc_Whh1 = (const float*)d_in[7];
    const float* enc_b1   = (const float*)d_in[8];
    const float* dec_emb  = (const float*)d_in[9];
    const float* dec_Wih0 = (const float*)d_in[10];
    const float* dec_Whh0 = (const float*)d_in[11];
    const float* dec_b0   = (const float*)d_in[12];
    const float* dec_Wih1 = (const float*)d_in[13];
    const float* dec_Whh1 = (const float*)d_in[14];
    const float* dec_b1   = (const float*)d_in[15];
    const float* out_W    = (const float*)d_in[16];
    const float* out_b    = (const float*)d_in[17];
    float* out = (float*)d_out;

    __nv_bfloat16 *dy1hi, *dy1lo, *wvhi, *wvlo;
    cudaGetSymbolAddress((void**)&dy1hi, s2s_dy1hi);
    cudaGetSymbolAddress((void**)&dy1lo, s2s_dy1lo);
    cudaGetSymbolAddress((void**)&wvhi,  s2s_wvhi);
    cudaGetSymbolAddress((void**)&wvlo,  s2s_wvlo);

    cudaFuncSetAttribute(s2s_lstm_persist,
                         cudaFuncAttributeMaxDynamicSharedMemorySize, SMEM_BYTES);
    cudaFuncSetAttribute(s2s_vgemm,
                         cudaFuncAttributeMaxDynamicSharedMemorySize, VSMEM);

    // 0: init
    s2s_init_kernel<<<s2s_grid(BATCH * VOCAB), 256>>>(out);
    // 1: embeddings
    s2s_embed_all<<<s2s_grid((S_LEN + T_STEPS) * BATCH * EMB), 256>>>(src, trg, enc_emb, dec_emb);
    // 2: x-projections
    s2s_xproj<<<dim3(XROWS / GBM, G4 / GBN), 256>>>(enc_Wih0, enc_b0, dec_Wih0, dec_b0);
    // 3: recurrence (ncu lands here)
    s2s_lstm_persist<<<NBLK, 512, SMEM_BYTES>>>(
        enc_Whh0, enc_Wih1, enc_Whh1, enc_b1,
        dec_Whh0, dec_Wih1, dec_Whh1, dec_b1);
    // 4: split out_W
    s2s_split_mat<<<s2s_grid(VOCAB * HID), 256>>>(out_W, wvhi, wvlo, VOCAB * HID);
    // 5: vocab projection (K-chunk 64)
    s2s_vgemm<<<dim3(MPAD / 128, VOCAB / 128), 256, VSMEM>>>(
        dy1hi, dy1lo, wvhi, wvlo, out_b, out, T_STEPS * BATCH);
}

// round 15
// speedup vs baseline: 1.1056x; 1.1056x over previous
#include <cuda_runtime.h>
#include <cuda_bf16.h>
#include <stdint.h>
#include <math.h>

#define S_LEN   50
#define T_STEPS 39
#define BATCH   32
#define EMB     256
#define HID     512
#define G4      2048
#define VOCAB   32000
#define NBLK    128
#define NGRP    64
#define MPAD    1280
#define XROWS   2944
#define DECOFF  1664

// ---------------- scratch (device globals) ----------------------------------
__device__ float s2s_x_all [XROWS * EMB];
__device__ float s2s_xw_all[XROWS * G4];
__device__ unsigned s2s_barA, s2s_barB;
__device__ __nv_bfloat16 s2s_h0hi [4 * BATCH * HID];
__device__ __nv_bfloat16 s2s_h0lo [4 * BATCH * HID];
__device__ __nv_bfloat16 s2s_acthi[4 * BATCH * 1024];
__device__ __nv_bfloat16 s2s_actlo[4 * BATCH * 1024];
__device__ __nv_bfloat16 s2s_dy1hi[MPAD * HID];
__device__ __nv_bfloat16 s2s_dy1lo[MPAD * HID];
__device__ __nv_bfloat16 s2s_wvhi [VOCAB * HID];
__device__ __nv_bfloat16 s2s_wvlo [VOCAB * HID];

// ---------------- helpers ----------------------------------------------------
__device__ __forceinline__ float s2s_sigm(float x) { return 1.0f / (1.0f + expf(-x)); }
__device__ __forceinline__ void s2s_split(float v, __nv_bfloat16* hi, __nv_bfloat16* lo) {
    __nv_bfloat16 h = __float2bfloat16(v);
    *hi = h;
    *lo = __float2bfloat16(v - __bfloat162float(h));
}
__device__ __forceinline__ uint32_t s2s_ld2(const __nv_bfloat16* p) {
    return *reinterpret_cast<const uint32_t*>(p);
}
__device__ __forceinline__ void s2s_mma(float* d, const uint32_t* a, const uint32_t* b) {
    asm volatile(
        "mma.sync.aligned.m16n8k16.row.col.f32.bf16.bf16.f32 "
        "{%0,%1,%2,%3}, {%4,%5,%6,%7}, {%8,%9}, {%0,%1,%2,%3};\n"
        : "+f"(d[0]), "+f"(d[1]), "+f"(d[2]), "+f"(d[3])
        : "r"(a[0]), "r"(a[1]), "r"(a[2]), "r"(a[3]), "r"(b[0]), "r"(b[1]));
}
__device__ __forceinline__ uint32_t s2s_smem_u32(const void* p) {
    uint32_t a;
    asm("{ .reg .u64 t; cvta.to.shared.u64 t, %1; cvt.u32.u64 %0, t; }" : "=r"(a) : "l"(p));
    return a;
}
__device__ __forceinline__ void s2s_ldsm4(uint32_t* r, uint32_t addr) {
    asm volatile("ldmatrix.sync.aligned.m8n8.x4.shared.b16 {%0,%1,%2,%3}, [%4];"
                 : "=r"(r[0]), "=r"(r[1]), "=r"(r[2]), "=r"(r[3]) : "r"(addr));
}
__device__ __forceinline__ void s2s_cpasync(uint32_t dst, const void* src) {
    asm volatile("cp.async.cg.shared.global [%0], [%1], 16;" :: "r"(dst), "l"(src) : "memory");
}
#define CP_COMMIT() asm volatile("cp.async.commit_group;" ::: "memory")
#define CP_WAIT1()  asm volatile("cp.async.wait_group 1;" ::: "memory")
#define CP_WAIT0()  asm volatile("cp.async.wait_group 0;" ::: "memory")
__device__ __forceinline__ void s2s_st16(__nv_bfloat16* p, __nv_bfloat16 v) {
    unsigned short u = *reinterpret_cast<unsigned short*>(&v);
    asm volatile("st.global.cg.u16 [%0], %1;" :: "l"(p), "h"(u) : "memory");
}

// ---------------- init / embed / split ---------------------------------------
__global__ void s2s_init_kernel(float* __restrict__ out) {
    int i = blockIdx.x * 256 + threadIdx.x;
    if (i < BATCH * VOCAB) out[i] = 0.0f;
    if (i < 4 * BATCH * HID)  { s2s_h0hi[i] = __nv_bfloat16(0.f); s2s_h0lo[i] = __nv_bfloat16(0.f); }
    if (i < 4 * BATCH * 1024) { s2s_acthi[i] = __nv_bfloat16(0.f); s2s_actlo[i] = __nv_bfloat16(0.f); }
    if (i < MPAD * HID)       { s2s_dy1hi[i] = __nv_bfloat16(0.f); s2s_dy1lo[i] = __nv_bfloat16(0.f); }
    if (i == 0) { s2s_barA = 0u; s2s_barB = 0u; }
}

__global__ void s2s_embed_all(const int* __restrict__ src, const int* __restrict__ trg,
                              const float* __restrict__ eemb, const float* __restrict__ demb) {
    int i = blockIdx.x * 256 + threadIdx.x;
    if (i >= (S_LEN + T_STEPS) * BATCH * EMB) return;
    int r = i >> 8, e = i & 255;
    if (r < S_LEN * BATCH)
        s2s_x_all[r * EMB + e] = eemb[(size_t)src[r] * EMB + e];
    else {
        int rd = r - S_LEN * BATCH;
        s2s_x_all[(DECOFF + rd) * EMB + e] = demb[(size_t)trg[rd] * EMB + e];
    }
}

__global__ void s2s_split_mat(const float* __restrict__ src, __nv_bfloat16* __restrict__ hi,
                              __nv_bfloat16* __restrict__ lo, int n) {
    int i = blockIdx.x * 256 + threadIdx.x;
    if (i >= n) return;
    float v = src[i];
    __nv_bfloat16 h = __float2bfloat16(v);
    hi[i] = h;
    lo[i] = __float2bfloat16(v - __bfloat162float(h));
}

// ---- combined x-projection (unchanged, passing) ------------------------------
#define GBM 128
#define GBN 64
#define GBK 32
#define GPAD 40

__global__ __launch_bounds__(256)
void s2s_xproj(const float* __restrict__ We, const float* __restrict__ be,
               const float* __restrict__ Wd, const float* __restrict__ bd) {
    __shared__ __nv_bfloat16 shA[2][GBM][GPAD];
    __shared__ __nv_bfloat16 shB[2][GBN][GPAD];
    const int tid = threadIdx.x;
    const int warp = tid >> 5, lane = tid & 31;
    const int wm = warp >> 1, wn = warp & 1;
    const int g = lane >> 2, tq = lane & 3;
    const int bm = blockIdx.x * GBM, bn = blockIdx.y * GBN;
    const int tr = tid >> 3, c4 = (tid & 7) * 4;

    const bool enc = (bm < DECOFF);
    const float* Bw   = enc ? We : Wd;
    const float* bias = enc ? be : bd;
    const int Ml      = enc ? (S_LEN * BATCH) : (DECOFF + T_STEPS * BATCH);
    const float* A = s2s_x_all;
    float* C = s2s_xw_all;
    const int K = EMB;

    float acc[2][4][4];
#pragma unroll
    for (int i = 0; i < 2; i++)
#pragma unroll
        for (int j = 0; j < 4; j++)
#pragma unroll
            for (int k = 0; k < 4; k++) acc[i][j][k] = 0.0f;

    float4 ra[4], rb[2];
#pragma unroll
    for (int q = 0; q < 4; q++) {
        int row = bm + q * 32 + tr;
        ra[q] = (row < Ml) ? *(const float4*)&A[(size_t)row * K + c4]
                           : make_float4(0.f, 0.f, 0.f, 0.f);
    }
#pragma unroll
    for (int q = 0; q < 2; q++)
        rb[q] = *(const float4*)&Bw[(size_t)(bn + q * 32 + tr) * K + c4];

    for (int ch = 0; ch < K / GBK; ch++) {
        __syncthreads();
#pragma unroll
        for (int q = 0; q < 4; q++) {
            const float* pv = (const float*)&ra[q];
#pragma unroll
            for (int j = 0; j < 4; j++)
                s2s_split(pv[j], &shA[0][q * 32 + tr][c4 + j], &shA[1][q * 32 + tr][c4 + j]);
        }
#pragma unroll
        for (int q = 0; q < 2; q++) {
            const float* pv = (const float*)&rb[q];
#pragma unroll
            for (int j = 0; j < 4; j++)
                s2s_split(pv[j], &shB[0][q * 32 + tr][c4 + j], &shB[1][q * 32 + tr][c4 + j]);
        }
        __syncthreads();
        if (ch + 1 < K / GBK) {
            int k0 = (ch + 1) * GBK;
#pragma unroll
            for (int q = 0; q < 4; q++) {
                int row = bm + q * 32 + tr;
                ra[q] = (row < Ml) ? *(const float4*)&A[(size_t)row * K + k0 + c4]
                                   : make_float4(0.f, 0.f, 0.f, 0.f);
            }
#pragma unroll
            for (int q = 0; q < 2; q++)
                rb[q] = *(const float4*)&Bw[(size_t)(bn + q * 32 + tr) * K + k0 + c4];
        }
#pragma unroll
        for (int kk = 0; kk < 2; kk++) {
            const int ko = kk * 16;
            uint32_t ah[2][4], al[2][4], bh[4][2], bl[4][2];
#pragma unroll
            for (int mt = 0; mt < 2; mt++) {
                int r0 = wm * 32 + mt * 16;
                ah[mt][0] = s2s_ld2(&shA[0][r0 + g][ko + 2 * tq]);
                ah[mt][1] = s2s_ld2(&shA[0][r0 + g + 8][ko + 2 * tq]);
                ah[mt][2] = s2s_ld2(&shA[0][r0 + g][ko + 2 * tq + 8]);
                ah[mt][3] = s2s_ld2(&shA[0][r0 + g + 8][ko + 2 * tq + 8]);
                al[mt][0] = s2s_ld2(&shA[1][r0 + g][ko + 2 * tq]);
                al[mt][1] = s2s_ld2(&shA[1][r0 + g + 8][ko + 2 * tq]);
                al[mt][2] = s2s_ld2(&shA[1][r0 + g][ko + 2 * tq + 8]);
                al[mt][3] = s2s_ld2(&shA[1][r0 + g + 8][ko + 2 * tq + 8]);
            }
#pragma unroll
            for (int nt = 0; nt < 4; nt++) {
                int rn = wn * 32 + nt * 8 + g;
                bh[nt][0] = s2s_ld2(&shB[0][rn][ko + 2 * tq]);
                bh[nt][1] = s2s_ld2(&shB[0][rn][ko + 2 * tq + 8]);
                bl[nt][0] = s2s_ld2(&shB[1][rn][ko + 2 * tq]);
                bl[nt][1] = s2s_ld2(&shB[1][rn][ko + 2 * tq + 8]);
            }
#pragma unroll
            for (int mt = 0; mt < 2; mt++)
#pragma unroll
                for (int nt = 0; nt < 4; nt++) {
                    s2s_mma(acc[mt][nt], ah[mt], bh[nt]);
                    s2s_mma(acc[mt][nt], ah[mt], bl[nt]);
                    s2s_mma(acc[mt][nt], al[mt], bh[nt]);
                }
        }
    }
#pragma unroll
    for (int mt = 0; mt < 2; mt++)
#pragma unroll
        for (int nt = 0; nt < 4; nt++) {
            int col = bn + wn * 32 + nt * 8 + 2 * tq;
            float b0v = bias[col], b1v = bias[col + 1];
            int r0 = bm + wm * 32 + mt * 16 + g;
            if (r0 < Ml) {
                float* p = &C[(size_t)r0 * G4 + col];
                p[0] = acc[mt][nt][0] + b0v;
                p[1] = acc[mt][nt][1] + b1v;
            }
            if (r0 + 8 < Ml) {
                float* p = &C[(size_t)(r0 + 8) * G4 + col];
                p[0] = acc[mt][nt][2] + b0v;
                p[1] = acc[mt][nt][3] + b1v;
            }
        }
}

// ---------------- persistent recurrence: gate-pair split-K (16 warps) ---------
#define WS 1032
#define AS 520
#define SMEM_BYTES 215040      // 198656 + 16KB shG
#define ABYTES (AS * 2)
#define WBYTES (WS * 2)

// gate-pair sweep: per kt2 load 4 A + 4 B LDSM, 12 mma (2 gates)
__device__ __forceinline__ void s2s_sweepG(uint32_t aHi, uint32_t aLo,
                                           uint32_t wHi, uint32_t wLo,
                                           int aoff, int boff0, int boff1, int kt0,
                                           float* acc0, float* acc1) {
#pragma unroll
    for (int kt2 = 0; kt2 < 4; kt2++) {
        const int k0b = (kt0 + kt2) * 64;
        uint32_t ah0[4], ah1[4], al0[4], al1[4];
        uint32_t bh0[4], bl0[4], bh1[4], bl1[4];
        s2s_ldsm4(ah0, aHi + aoff + k0b);
        s2s_ldsm4(ah1, aHi + aoff + k0b + 32);
        s2s_ldsm4(al0, aLo + aoff + k0b);
        s2s_ldsm4(al1, aLo + aoff + k0b + 32);
        s2s_ldsm4(bh0, wHi + boff0 + k0b);
        s2s_ldsm4(bl0, wLo + boff0 + k0b);
        s2s_ldsm4(bh1, wHi + boff1 + k0b);
        s2s_ldsm4(bl1, wLo + boff1 + k0b);
        s2s_mma(acc0, ah0, bh0);
        s2s_mma(acc0, ah0, bl0);
        s2s_mma(acc0, al0, bh0);
        s2s_mma(acc0, ah1, bh0 + 2);
        s2s_mma(acc0, ah1, bl0 + 2);
        s2s_mma(acc0, al1, bh0 + 2);
        s2s_mma(acc1, ah0, bh1);
        s2s_mma(acc1, ah0, bl1);
        s2s_mma(acc1, al0, bh1);
        s2s_mma(acc1, ah1, bh1 + 2);
        s2s_mma(acc1, ah1, bl1 + 2);
        s2s_mma(acc1, al1, bh1 + 2);
    }
}

__global__ __launch_bounds__(512, 1)
void s2s_lstm_persist(const float* __restrict__ eWhh0, const float* __restrict__ eWih1,
                      const float* __restrict__ eWhh1, const float* __restrict__ eb1,
                      const float* __restrict__ dWhh0, const float* __restrict__ dWih1,
                      const float* __restrict__ dWhh1, const float* __restrict__ db1) {
    extern __shared__ __nv_bfloat16 sm[];
    __nv_bfloat16* whi = sm;
    __nv_bfloat16* wlo = sm + 33024;
    __nv_bfloat16* ahi = sm + 66048;
    __nv_bfloat16* alo = sm + 82688;
    float* shG = (float*)(sm + 99328);          // float[4][4][256] = 16KB
    const uint32_t aHiB = s2s_smem_u32(ahi), aLoB = s2s_smem_u32(alo);
    const uint32_t wHiB = s2s_smem_u32(whi), wLoB = s2s_smem_u32(wlo);

    const int tid = threadIdx.x, warp = tid >> 5, lane = tid & 31;
    const int kq = warp >> 2;                   // K-quarter (0..3)
    const int mt = (warp >> 1) & 1, gp = warp & 1;
    const int g = lane >> 2, tq = lane & 3;
    const bool isA = blockIdx.x < NGRP;
    const int u0 = (isA ? blockIdx.x : blockIdx.x - NGRP) * 8;
    const int lrow = (tid & 255) >> 3, c4 = (tid & 7) * 4;
    const int WR = (lrow >> 3) * HID + u0 + (lrow & 7);
    const int eb = (tid & 255) >> 3, eu = tid & 7;
    const int U = u0 + eu;
    const int aoff  = (mt * 16 + (lane & 15)) * ABYTES + ((lane >> 4) << 4);
    const int boff0 = ((2 * gp) * 8 + (lane & 7)) * WBYTES + ((lane >> 3) << 4);
    const int boff1 = ((2 * gp + 1) * 8 + (lane & 7)) * WBYTES + ((lane >> 3) << 4);
    const bool low = (tid < 256);

    float creg = 0.0f;
    unsigned iter = 0;

    for (int phase = 0; phase < 2; phase++) {
        const float* Whh0 = phase ? dWhh0 : eWhh0;
        const float* Wih1 = phase ? dWih1 : eWih1;
        const float* Whh1 = phase ? dWhh1 : eWhh1;
        const float* bb1  = phase ? db1  : eb1;
        const float* xw   = s2s_xw_all + (phase ? (size_t)DECOFF * G4 : 0);
        const int steps   = phase ? T_STEPS : S_LEN;
        const int gbase   = phase ? S_LEN : 0;

        float bi1 = 0.f, bf1 = 0.f, bc1 = 0.f, bo1 = 0.f;
        if (!isA && low) {
            bi1 = __ldg(&bb1[U]); bf1 = __ldg(&bb1[HID + U]);
            bc1 = __ldg(&bb1[2 * HID + U]); bo1 = __ldg(&bb1[3 * HID + U]);
        }

        if (low) {
            if (isA) {
                for (int col = c4; col < HID; col += 32) {
                    float4 v = *(const float4*)&Whh0[(size_t)WR * HID + col];
                    const float* pv = (const float*)&v;
#pragma unroll
                    for (int i = 0; i < 4; i++)
                        s2s_split(pv[i], &whi[lrow * WS + col + i], &wlo[lrow * WS + col + i]);
                }
            } else {
                for (int col = c4; col < HID; col += 32) {
                    float4 v = *(const float4*)&Wih1[(size_t)WR * HID + col];
                    const float* pv = (const float*)&v;
#pragma unroll
                    for (int i = 0; i < 4; i++)
                        s2s_split(pv[i], &whi[lrow * WS + col + i], &wlo[lrow * WS + col + i]);
                    float4 v2 = *(const float4*)&Whh1[(size_t)WR * HID + col];
                    const float* pw = (const float*)&v2;
#pragma unroll
                    for (int i = 0; i < 4; i++)
                        s2s_split(pw[i], &whi[lrow * WS + 512 + col + i], &wlo[lrow * WS + 512 + col + i]);
                }
            }
        }
        __syncthreads();

        for (int j = 0; j <= steps; j++) {
            const bool act_me = isA ? (j < steps) : (j >= 1);
            if (act_me) {
                float acc0[4] = {0.f, 0.f, 0.f, 0.f};
                float acc1[4] = {0.f, 0.f, 0.f, 0.f};
                if (isA) {
                    const int gs = gbase + j;
                    const int rs = (gs + 3) & 3, ws = gs & 3;
                    const __nv_bfloat16* gHi = s2s_h0hi + (size_t)rs * BATCH * HID;
                    const __nv_bfloat16* gLo = s2s_h0lo + (size_t)rs * BATCH * HID;
#pragma unroll
                    for (int v = 0; v < 4; v++) {
                        int idx = tid + v * 512;
                        int row = idx >> 6, col = (idx & 63) * 8;
                        uint32_t d = (uint32_t)(row * ABYTES + col * 2);
                        s2s_cpasync(aHiB + d, gHi + (size_t)row * HID + col);
                        s2s_cpasync(aLoB + d, gLo + (size_t)row * HID + col);
                    }
                    CP_COMMIT();
                    float xg0 = 0.f, xg1 = 0.f, xg2 = 0.f, xg3 = 0.f;
                    if (low) {
                        const float* xwt = xw + (size_t)j * BATCH * G4 + (size_t)eb * G4;
                        xg0 = __ldg(&xwt[U]); xg1 = __ldg(&xwt[HID + U]);
                        xg2 = __ldg(&xwt[2 * HID + U]); xg3 = __ldg(&xwt[3 * HID + U]);
                    }
                    CP_WAIT0();
                    __syncthreads();
                    s2s_sweepG(aHiB, aLoB, wHiB, wLoB, aoff, boff0, boff1, kq * 4, acc0, acc1);
                    {
                        float* sg = shG + kq * 1024;
                        float* s0 = sg + (2 * gp) * 256;
                        float* s1 = sg + (2 * gp + 1) * 256;
                        s0[(mt * 16 + g) * 8 + 2 * tq]         = acc0[0];
                        s0[(mt * 16 + g) * 8 + 2 * tq + 1]     = acc0[1];
                        s0[(mt * 16 + g + 8) * 8 + 2 * tq]     = acc0[2];
                        s0[(mt * 16 + g + 8) * 8 + 2 * tq + 1] = acc0[3];
                        s1[(mt * 16 + g) * 8 + 2 * tq]         = acc1[0];
                        s1[(mt * 16 + g) * 8 + 2 * tq + 1]     = acc1[1];
                        s1[(mt * 16 + g + 8) * 8 + 2 * tq]     = acc1[2];
                        s1[(mt * 16 + g + 8) * 8 + 2 * tq + 1] = acc1[3];
                    }
                    __syncthreads();
                    if (low) {
                        const int o = eb * 8 + eu;
                        float gi = xg0, gf = xg1, gc = xg2, go = xg3;
#pragma unroll
                        for (int q = 0; q < 4; q++) {
                            gi += shG[q * 1024 + 0 * 256 + o];
                            gf += shG[q * 1024 + 1 * 256 + o];
                            gc += shG[q * 1024 + 2 * 256 + o];
                            go += shG[q * 1024 + 3 * 256 + o];
                        }
                        creg = s2s_sigm(gf) * creg + s2s_sigm(gi) * tanhf(gc);
                        float h = s2s_sigm(go) * tanhf(creg);
                        __nv_bfloat16 hh, hl;
                        s2s_split(h, &hh, &hl);
                        const size_t o1 = (size_t)ws * BATCH * HID + eb * HID + U;
                        const size_t o2 = (size_t)ws * BATCH * 1024 + eb * 1024 + U;
                        s2s_st16(&s2s_h0hi[o1], hh);  s2s_st16(&s2s_h0lo[o1], hl);
                        s2s_st16(&s2s_acthi[o2], hh); s2s_st16(&s2s_actlo[o2], hl);
                    }
                } else {
                    const int gs2 = gbase + j - 1;
                    const int sy = gs2 & 3, sh = (gs2 + 3) & 3, ws2 = gs2 & 3;
                    const __nv_bfloat16* yHi = s2s_acthi + (size_t)sy * BATCH * 1024;
                    const __nv_bfloat16* yLo = s2s_actlo + (size_t)sy * BATCH * 1024;
                    const __nv_bfloat16* hHi = s2s_acthi + (size_t)sh * BATCH * 1024;
                    const __nv_bfloat16* hLo = s2s_actlo + (size_t)sh * BATCH * 1024;
#pragma unroll
                    for (int v = 0; v < 4; v++) {
                        int idx = tid + v * 512;
                        int row = idx >> 6, col = (idx & 63) * 8;
                        uint32_t d = (uint32_t)(row * ABYTES + col * 2);
                        s2s_cpasync(aHiB + d, yHi + (size_t)row * 1024 + col);
                        s2s_cpasync(aLoB + d, yLo + (size_t)row * 1024 + col);
                    }
                    CP_COMMIT();
                    uint4 rh[4], rl[4];
#pragma unroll
                    for (int v = 0; v < 4; v++) {
                        int idx = tid + v * 512;
                        int row = idx >> 6, col = (idx & 63) * 8;
                        rh[v] = __ldcg((const uint4*)(hHi + (size_t)row * 1024 + 512 + col));
                        rl[v] = __ldcg((const uint4*)(hLo + (size_t)row * 1024 + 512 + col));
                    }
                    CP_WAIT0();
                    __syncthreads();
                    s2s_sweepG(aHiB, aLoB, wHiB, wLoB, aoff, boff0, boff1, kq * 4, acc0, acc1);
                    __syncthreads();
#pragma unroll
                    for (int v = 0; v < 4; v++) {
                        int idx = tid + v * 512;
                        int row = idx >> 6, col = (idx & 63) * 8;
                        uint32_t d = (uint32_t)(row * ABYTES + col * 2);
                        *(uint4*)((char*)ahi + d) = rh[v];
                        *(uint4*)((char*)alo + d) = rl[v];
                    }
                    __syncthreads();
                    s2s_sweepG(aHiB, aLoB, wHiB + 1024, wLoB + 1024, aoff, boff0, boff1, kq * 4, acc0, acc1);
                    {
                        float* sg = shG + kq * 1024;
                        float* s0 = sg + (2 * gp) * 256;
                        float* s1 = sg + (2 * gp + 1) * 256;
                        s0[(mt * 16 + g) * 8 + 2 * tq]         = acc0[0];
                        s0[(mt * 16 + g) * 8 + 2 * tq + 1]     = acc0[1];
                        s0[(mt * 16 + g + 8) * 8 + 2 * tq]     = acc0[2];
                        s0[(mt * 16 + g + 8) * 8 + 2 * tq + 1] = acc0[3];
                        s1[(mt * 16 + g) * 8 + 2 * tq]         = acc1[0];
                        s1[(mt * 16 + g) * 8 + 2 * tq + 1]     = acc1[1];
                        s1[(mt * 16 + g + 8) * 8 + 2 * tq]     = acc1[2];
                        s1[(mt * 16 + g + 8) * 8 + 2 * tq + 1] = acc1[3];
                    }
                    __syncthreads();
                    if (low) {
                        const int o = eb * 8 + eu;
                        float gi = bi1, gf = bf1, gc = bc1, go = bo1;
#pragma unroll
                        for (int q = 0; q < 4; q++) {
                            gi += shG[q * 1024 + 0 * 256 + o];
                            gf += shG[q * 1024 + 1 * 256 + o];
                            gc += shG[q * 1024 + 2 * 256 + o];
                            go += shG[q * 1024 + 3 * 256 + o];
                        }
                        creg = s2s_sigm(gf) * creg + s2s_sigm(gi) * tanhf(gc);
                        float h = s2s_sigm(go) * tanhf(creg);
                        __nv_bfloat16 hh, hl;
                        s2s_split(h, &hh, &hl);
                        const size_t o2 = (size_t)ws2 * BATCH * 1024 + eb * 1024 + 512 + U;
                        s2s_st16(&s2s_acthi[o2], hh); s2s_st16(&s2s_actlo[o2], hl);
                        if (phase == 1) {
                            const size_t od = (size_t)(j - 1) * BATCH * HID + eb * HID + U;
                            s2s_dy1hi[od] = hh;
                            s2s_dy1lo[od] = hl;
                        }
                    }
                }
            }
            iter++;
            __syncthreads();
            if (tid == 0) {
                __threadfence();
                unsigned* myB = isA ? &s2s_barA : &s2s_barB;
                atomicAdd(myB, 1u);
                while (*(volatile unsigned*)myB < iter * NGRP) { }
                if (isA) {
                    if (iter > 3)
                        while (*(volatile unsigned*)&s2s_barB < (iter - 3) * NGRP) { }
                } else {
                    while (*(volatile unsigned*)&s2s_barA < iter * NGRP) { }
                }
                __threadfence();
            }
            __syncthreads();
        }
    }
}

// ---------------- vocab projection: PROVEN R13 256-thread K-32 version -------
#define VTILE  8192
#define VSTAGE 32768
#define VSMEM  65536

__device__ __forceinline__ uint32_t s2s_vswz(int row, int c16) {
    return (uint32_t)(row * 64 + ((c16 ^ ((row >> 1) & 3)) << 4));
}

__global__ __launch_bounds__(256)
void s2s_vgemm(const __nv_bfloat16* __restrict__ Ahi, const __nv_bfloat16* __restrict__ Alo,
               const __nv_bfloat16* __restrict__ Bhi, const __nv_bfloat16* __restrict__ Blo,
               const float* __restrict__ bias, float* __restrict__ C, int Mvalid) {
    extern __shared__ char vsm[];
    const uint32_t sb = s2s_smem_u32(vsm);
    const int tid = threadIdx.x, wid = tid >> 5, lane = tid & 31;
    const int wm = wid >> 2, wn = wid & 3;
    const int g = lane >> 2, tq = lane & 3;
    const int bm = blockIdx.x * 128, bn = blockIdx.y * 128;

    const __nv_bfloat16* srcs[4] = {
        Ahi + (size_t)bm * HID, Alo + (size_t)bm * HID,
        Bhi + (size_t)bn * HID, Blo + (size_t)bn * HID };

    auto prefetch = [&](int ch, int st) {
#pragma unroll
        for (int t = 0; t < 4; t++) {
#pragma unroll
            for (int v = 0; v < 2; v++) {
                int idx = tid + v * 256;
                int row = idx >> 2, c16 = idx & 3;
                const __nv_bfloat16* gp = srcs[t] + (size_t)row * HID + ch * 32 + c16 * 8;
                s2s_cpasync(sb + st * VSTAGE + t * VTILE + s2s_vswz(row, c16), gp);
            }
        }
    };

    float acc[4][4][4];
#pragma unroll
    for (int i = 0; i < 4; i++)
#pragma unroll
        for (int j = 0; j < 4; j++)
#pragma unroll
            for (int k = 0; k < 4; k++) acc[i][j][k] = 0.0f;

    prefetch(0, 0);
    CP_COMMIT();

    for (int ch = 0; ch < 16; ch++) {
        const int st = ch & 1;
        if (ch + 1 < 16) { prefetch(ch + 1, st ^ 1); CP_COMMIT(); }
        if (ch + 1 < 16) { CP_WAIT1(); } else { CP_WAIT0(); }
        __syncthreads();

        const uint32_t base = sb + st * VSTAGE;
#pragma unroll
        for (int kk = 0; kk < 2; kk++) {
            uint32_t ah[4][4], al[4][4], bh2[2][4], bl2[2][4];
            const int arow = wm * 64 + (lane & 15);
            const int ac16 = kk * 2 + (lane >> 4);
#pragma unroll
            for (int mt = 0; mt < 4; mt++) {
                const uint32_t off = s2s_vswz(arow + mt * 16, ac16);
                s2s_ldsm4(ah[mt], base + off);
                s2s_ldsm4(al[mt], base + VTILE + off);
            }
            const int brow = wn * 32 + ((lane >> 4) << 3) + (lane & 7);
            const int bc16 = kk * 2 + ((lane >> 3) & 1);
#pragma unroll
            for (int nt2 = 0; nt2 < 2; nt2++) {
                const uint32_t off = s2s_vswz(brow + nt2 * 16, bc16);
                s2s_ldsm4(bh2[nt2], base + 2 * VTILE + off);
                s2s_ldsm4(bl2[nt2], base + 3 * VTILE + off);
            }
#pragma unroll
            for (int mt = 0; mt < 4; mt++)
#pragma unroll
                for (int nt = 0; nt < 4; nt++) {
                    const uint32_t* bh = &bh2[nt >> 1][(nt & 1) * 2];
                    const uint32_t* bl = &bl2[nt >> 1][(nt & 1) * 2];
                    s2s_mma(acc[mt][nt], ah[mt], bh);
                    s2s_mma(acc[mt][nt], ah[mt], bl);
                    s2s_mma(acc[mt][nt], al[mt], bh);
                }
        }
        __syncthreads();
    }

#pragma unroll
    for (int mt = 0; mt < 4; mt++) {
#pragma unroll
        for (int nt = 0; nt < 4; nt++) {
            const int col = bn + wn * 32 + nt * 8 + 2 * tq;
            const float b0 = bias[col], b1 = bias[col + 1];
            const int r0 = bm + wm * 64 + mt * 16 + g;
            if (r0 < Mvalid) {
                float2 o = { acc[mt][nt][0] + b0, acc[mt][nt][1] + b1 };
                *(float2*)&C[(size_t)(r0 + BATCH) * VOCAB + col] = o;
            }
            if (r0 + 8 < Mvalid) {
                float2 o = { acc[mt][nt][2] + b0, acc[mt][nt][3] + b1 };
                *(float2*)&C[(size_t)(r0 + 8 + BATCH) * VOCAB + col] = o;
            }
        }
    }
}

static inline int s2s_grid(int n) { return (n + 255) / 256; }

extern "C" void kernel_launch(void* const* d_in, const int* in_sizes, int n_in,
                              void* d_out, int out_size) {
    (void)in_sizes; (void)n_in; (void)out_size;
    const int*   src      = (const int*)  d_in[0];
    const int*   trg      = (const int*)  d_in[1];
    const float* enc_emb  = (const float*)d_in[2];
    const float* enc_Wih0 = (const float*)d_in[3];
    const float* enc_Whh0 = (const float*)d_in[4];
    const float* enc_b0   = (const float*)d_in[5];
    const float* enc_Wih1 = (const float*)d_in[6];
    const float* enc_Whh1 = (const float*)d_in[7];
    const float* enc_b1   = (const float*)d_in[8];
    const float* dec_emb  = (const float*)d_in[9];
    const float* dec_Wih0 = (const float*)d_in[10];
    const float* dec_Whh0 = (const float*)d_in[11];
    const float* dec_b0   = (const float*)d_in[12];
    const float* dec_Wih1 = (const float*)d_in[13];
    const float* dec_Whh1 = (const float*)d_in[14];
    const float* dec_b1   = (const float*)d_in[15];
    const float* out_W    = (const float*)d_in[16];
    const float* out_b    = (const float*)d_in[17];
    float* out = (float*)d_out;

    __nv_bfloat16 *dy1hi, *dy1lo, *wvhi, *wvlo;
    cudaGetSymbolAddress((void**)&dy1hi, s2s_dy1hi);
    cudaGetSymbolAddress((void**)&dy1lo, s2s_dy1lo);
    cudaGetSymbolAddress((void**)&wvhi,  s2s_wvhi);
    cudaGetSymbolAddress((void**)&wvlo,  s2s_wvlo);

    cudaFuncSetAttribute(s2s_lstm_persist,
                         cudaFuncAttributeMaxDynamicSharedMemorySize, SMEM_BYTES);
    cudaFuncSetAttribute(s2s_vgemm,
                         cudaFuncAttributeMaxDynamicSharedMemorySize, VSMEM);

    // 0: init
    s2s_init_kernel<<<s2s_grid(BATCH * VOCAB), 256>>>(out);
    // 1: embeddings
    s2s_embed_all<<<s2s_grid((S_LEN + T_STEPS) * BATCH * EMB), 256>>>(src, trg, enc_emb, dec_emb);
    // 2: x-projections
    s2s_xproj<<<dim3(XROWS / GBM, G4 / GBN), 256>>>(enc_Wih0, enc_b0, dec_Wih0, dec_b0);
    // 3: recurrence (gate-pair split-K; ncu lands here)
    s2s_lstm_persist<<<NBLK, 512, SMEM_BYTES>>>(
        enc_Whh0, enc_Wih1, enc_Whh1, enc_b1,
        dec_Whh0, dec_Wih1, dec_Whh1, dec_b1);
    // 4: split out_W
    s2s_split_mat<<<s2s_grid(VOCAB * HID), 256>>>(out_W, wvhi, wvlo, VOCAB * HID);
    // 5: vocab projection (proven R13 version)
    s2s_vgemm<<<dim3(MPAD / 128, VOCAB / 128), 256, VSMEM>>>(
        dy1hi, dy1lo, wvhi, wvlo, out_b, out, T_STEPS * BATCH);
}

// round 16
// speedup vs baseline: 1.1179x; 1.0111x over previous
#include <cuda_runtime.h>
#include <cuda_bf16.h>
#include <stdint.h>
#include <math.h>

#define S_LEN   50
#define T_STEPS 39
#define BATCH   32
#define EMB     256
#define HID     512
#define G4      2048
#define VOCAB   32000
#define NBLK    128
#define NGRP    64
#define MPAD    1280
#define XROWS   2944
#define DECOFF  1664

// ---------------- scratch (device globals) ----------------------------------
__device__ float s2s_x_all [XROWS * EMB];
__device__ float s2s_xw_all[XROWS * G4];
__device__ unsigned s2s_barA, s2s_barB;
__device__ __nv_bfloat16 s2s_h0hi [4 * BATCH * HID];
__device__ __nv_bfloat16 s2s_h0lo [4 * BATCH * HID];
__device__ __nv_bfloat16 s2s_acthi[4 * BATCH * 1024];
__device__ __nv_bfloat16 s2s_actlo[4 * BATCH * 1024];
__device__ __nv_bfloat16 s2s_dy1hi[MPAD * HID];
__device__ __nv_bfloat16 s2s_dy1lo[MPAD * HID];
__device__ __nv_bfloat16 s2s_wvhi [VOCAB * HID];
__device__ __nv_bfloat16 s2s_wvlo [VOCAB * HID];

// ---------------- helpers ----------------------------------------------------
__device__ __forceinline__ float s2s_sigm(float x) { return 1.0f / (1.0f + __expf(-x)); }
__device__ __forceinline__ float s2s_tanh(float x) {
    // tanh(x) = 2*sigmoid(2x) - 1 with fast exp: ~1e-6 rel err
    return 2.0f / (1.0f + __expf(-2.0f * x)) - 1.0f;
}
__device__ __forceinline__ void s2s_split(float v, __nv_bfloat16* hi, __nv_bfloat16* lo) {
    __nv_bfloat16 h = __float2bfloat16(v);
    *hi = h;
    *lo = __float2bfloat16(v - __bfloat162float(h));
}
__device__ __forceinline__ uint32_t s2s_ld2(const __nv_bfloat16* p) {
    return *reinterpret_cast<const uint32_t*>(p);
}
__device__ __forceinline__ void s2s_mma(float* d, const uint32_t* a, const uint32_t* b) {
    asm volatile(
        "mma.sync.aligned.m16n8k16.row.col.f32.bf16.bf16.f32 "
        "{%0,%1,%2,%3}, {%4,%5,%6,%7}, {%8,%9}, {%0,%1,%2,%3};\n"
        : "+f"(d[0]), "+f"(d[1]), "+f"(d[2]), "+f"(d[3])
        : "r"(a[0]), "r"(a[1]), "r"(a[2]), "r"(a[3]), "r"(b[0]), "r"(b[1]));
}
__device__ __forceinline__ uint32_t s2s_smem_u32(const void* p) {
    uint32_t a;
    asm("{ .reg .u64 t; cvta.to.shared.u64 t, %1; cvt.u32.u64 %0, t; }" : "=r"(a) : "l"(p));
    return a;
}
__device__ __forceinline__ void s2s_ldsm4(uint32_t* r, uint32_t addr) {
    asm volatile("ldmatrix.sync.aligned.m8n8.x4.shared.b16 {%0,%1,%2,%3}, [%4];"
                 : "=r"(r[0]), "=r"(r[1]), "=r"(r[2]), "=r"(r[3]) : "r"(addr));
}
__device__ __forceinline__ void s2s_cpasync(uint32_t dst, const void* src) {
    asm volatile("cp.async.cg.shared.global [%0], [%1], 16;" :: "r"(dst), "l"(src) : "memory");
}
#define CP_COMMIT() asm volatile("cp.async.commit_group;" ::: "memory")
#define CP_WAIT1()  asm volatile("cp.async.wait_group 1;" ::: "memory")
#define CP_WAIT0()  asm volatile("cp.async.wait_group 0;" ::: "memory")
__device__ __forceinline__ void s2s_st16(__nv_bfloat16* p, __nv_bfloat16 v) {
    unsigned short u = *reinterpret_cast<unsigned short*>(&v);
    asm volatile("st.global.cg.u16 [%0], %1;" :: "l"(p), "h"(u) : "memory");
}

// ---------------- init / embed / split ---------------------------------------
__global__ void s2s_init_kernel(float* __restrict__ out) {
    int i = blockIdx.x * 256 + threadIdx.x;
    if (i < BATCH * VOCAB) out[i] = 0.0f;
    if (i < 4 * BATCH * HID)  { s2s_h0hi[i] = __nv_bfloat16(0.f); s2s_h0lo[i] = __nv_bfloat16(0.f); }
    if (i < 4 * BATCH * 1024) { s2s_acthi[i] = __nv_bfloat16(0.f); s2s_actlo[i] = __nv_bfloat16(0.f); }
    if (i < MPAD * HID)       { s2s_dy1hi[i] = __nv_bfloat16(0.f); s2s_dy1lo[i] = __nv_bfloat16(0.f); }
    if (i == 0) { s2s_barA = 0u; s2s_barB = 0u; }
}

__global__ void s2s_embed_all(const int* __restrict__ src, const int* __restrict__ trg,
                              const float* __restrict__ eemb, const float* __restrict__ demb) {
    int i = blockIdx.x * 256 + threadIdx.x;
    if (i >= (S_LEN + T_STEPS) * BATCH * EMB) return;
    int r = i >> 8, e = i & 255;
    if (r < S_LEN * BATCH)
        s2s_x_all[r * EMB + e] = eemb[(size_t)src[r] * EMB + e];
    else {
        int rd = r - S_LEN * BATCH;
        s2s_x_all[(DECOFF + rd) * EMB + e] = demb[(size_t)trg[rd] * EMB + e];
    }
}

__global__ void s2s_split_mat(const float* __restrict__ src, __nv_bfloat16* __restrict__ hi,
                              __nv_bfloat16* __restrict__ lo, int n) {
    int i = blockIdx.x * 256 + threadIdx.x;
    if (i >= n) return;
    float v = src[i];
    __nv_bfloat16 h = __float2bfloat16(v);
    hi[i] = h;
    lo[i] = __float2bfloat16(v - __bfloat162float(h));
}

// ---- combined x-projection (unchanged, passing) ------------------------------
#define GBM 128
#define GBN 64
#define GBK 32
#define GPAD 40

__global__ __launch_bounds__(256)
void s2s_xproj(const float* __restrict__ We, const float* __restrict__ be,
               const float* __restrict__ Wd, const float* __restrict__ bd) {
    __shared__ __nv_bfloat16 shA[2][GBM][GPAD];
    __shared__ __nv_bfloat16 shB[2][GBN][GPAD];
    const int tid = threadIdx.x;
    const int warp = tid >> 5, lane = tid & 31;
    const int wm = warp >> 1, wn = warp & 1;
    const int g = lane >> 2, tq = lane & 3;
    const int bm = blockIdx.x * GBM, bn = blockIdx.y * GBN;
    const int tr = tid >> 3, c4 = (tid & 7) * 4;

    const bool enc = (bm < DECOFF);
    const float* Bw   = enc ? We : Wd;
    const float* bias = enc ? be : bd;
    const int Ml      = enc ? (S_LEN * BATCH) : (DECOFF + T_STEPS * BATCH);
    const float* A = s2s_x_all;
    float* C = s2s_xw_all;
    const int K = EMB;

    float acc[2][4][4];
#pragma unroll
    for (int i = 0; i < 2; i++)
#pragma unroll
        for (int j = 0; j < 4; j++)
#pragma unroll
            for (int k = 0; k < 4; k++) acc[i][j][k] = 0.0f;

    float4 ra[4], rb[2];
#pragma unroll
    for (int q = 0; q < 4; q++) {
        int row = bm + q * 32 + tr;
        ra[q] = (row < Ml) ? *(const float4*)&A[(size_t)row * K + c4]
                           : make_float4(0.f, 0.f, 0.f, 0.f);
    }
#pragma unroll
    for (int q = 0; q < 2; q++)
        rb[q] = *(const float4*)&Bw[(size_t)(bn + q * 32 + tr) * K + c4];

    for (int ch = 0; ch < K / GBK; ch++) {
        __syncthreads();
#pragma unroll
        for (int q = 0; q < 4; q++) {
            const float* pv = (const float*)&ra[q];
#pragma unroll
            for (int j = 0; j < 4; j++)
                s2s_split(pv[j], &shA[0][q * 32 + tr][c4 + j], &shA[1][q * 32 + tr][c4 + j]);
        }
#pragma unroll
        for (int q = 0; q < 2; q++) {
            const float* pv = (const float*)&rb[q];
#pragma unroll
            for (int j = 0; j < 4; j++)
                s2s_split(pv[j], &shB[0][q * 32 + tr][c4 + j], &shB[1][q * 32 + tr][c4 + j]);
        }
        __syncthreads();
        if (ch + 1 < K / GBK) {
            int k0 = (ch + 1) * GBK;
#pragma unroll
            for (int q = 0; q < 4; q++) {
                int row = bm + q * 32 + tr;
                ra[q] = (row < Ml) ? *(const float4*)&A[(size_t)row * K + k0 + c4]
                                   : make_float4(0.f, 0.f, 0.f, 0.f);
            }
#pragma unroll
            for (int q = 0; q < 2; q++)
                rb[q] = *(const float4*)&Bw[(size_t)(bn + q * 32 + tr) * K + k0 + c4];
        }
#pragma unroll
        for (int kk = 0; kk < 2; kk++) {
            const int ko = kk * 16;
            uint32_t ah[2][4], al[2][4], bh[4][2], bl[4][2];
#pragma unroll
            for (int mt = 0; mt < 2; mt++) {
                int r0 = wm * 32 + mt * 16;
                ah[mt][0] = s2s_ld2(&shA[0][r0 + g][ko + 2 * tq]);
                ah[mt][1] = s2s_ld2(&shA[0][r0 + g + 8][ko + 2 * tq]);
                ah[mt][2] = s2s_ld2(&shA[0][r0 + g][ko + 2 * tq + 8]);
                ah[mt][3] = s2s_ld2(&shA[0][r0 + g + 8][ko + 2 * tq + 8]);
                al[mt][0] = s2s_ld2(&shA[1][r0 + g][ko + 2 * tq]);
                al[mt][1] = s2s_ld2(&shA[1][r0 + g + 8][ko + 2 * tq]);
                al[mt][2] = s2s_ld2(&shA[1][r0 + g][ko + 2 * tq + 8]);
                al[mt][3] = s2s_ld2(&shA[1][r0 + g + 8][ko + 2 * tq + 8]);
            }
#pragma unroll
            for (int nt = 0; nt < 4; nt++) {
                int rn = wn * 32 + nt * 8 + g;
                bh[nt][0] = s2s_ld2(&shB[0][rn][ko + 2 * tq]);
                bh[nt][1] = s2s_ld2(&shB[0][rn][ko + 2 * tq + 8]);
                bl[nt][0] = s2s_ld2(&shB[1][rn][ko + 2 * tq]);
                bl[nt][1] = s2s_ld2(&shB[1][rn][ko + 2 * tq + 8]);
            }
#pragma unroll
            for (int mt = 0; mt < 2; mt++)
#pragma unroll
                for (int nt = 0; nt < 4; nt++) {
                    s2s_mma(acc[mt][nt], ah[mt], bh[nt]);
                    s2s_mma(acc[mt][nt], ah[mt], bl[nt]);
                    s2s_mma(acc[mt][nt], al[mt], bh[nt]);
                }
        }
    }
#pragma unroll
    for (int mt = 0; mt < 2; mt++)
#pragma unroll
        for (int nt = 0; nt < 4; nt++) {
            int col = bn + wn * 32 + nt * 8 + 2 * tq;
            float b0v = bias[col], b1v = bias[col + 1];
            int r0 = bm + wm * 32 + mt * 16 + g;
            if (r0 < Ml) {
                float* p = &C[(size_t)r0 * G4 + col];
                p[0] = acc[mt][nt][0] + b0v;
                p[1] = acc[mt][nt][1] + b1v;
            }
            if (r0 + 8 < Ml) {
                float* p = &C[(size_t)(r0 + 8) * G4 + col];
                p[0] = acc[mt][nt][2] + b0v;
                p[1] = acc[mt][nt][3] + b1v;
            }
        }
}

// ---------------- persistent recurrence: gate-pair split-K (R15, passing) -----
#define WS 1032
#define AS 520
#define SMEM_BYTES 215040
#define ABYTES (AS * 2)
#define WBYTES (WS * 2)

__device__ __forceinline__ void s2s_sweepG(uint32_t aHi, uint32_t aLo,
                                           uint32_t wHi, uint32_t wLo,
                                           int aoff, int boff0, int boff1, int kt0,
                                           float* acc0, float* acc1) {
#pragma unroll
    for (int kt2 = 0; kt2 < 4; kt2++) {
        const int k0b = (kt0 + kt2) * 64;
        uint32_t ah0[4], ah1[4], al0[4], al1[4];
        uint32_t bh0[4], bl0[4], bh1[4], bl1[4];
        s2s_ldsm4(ah0, aHi + aoff + k0b);
        s2s_ldsm4(ah1, aHi + aoff + k0b + 32);
        s2s_ldsm4(al0, aLo + aoff + k0b);
        s2s_ldsm4(al1, aLo + aoff + k0b + 32);
        s2s_ldsm4(bh0, wHi + boff0 + k0b);
        s2s_ldsm4(bl0, wLo + boff0 + k0b);
        s2s_ldsm4(bh1, wHi + boff1 + k0b);
        s2s_ldsm4(bl1, wLo + boff1 + k0b);
        s2s_mma(acc0, ah0, bh0);
        s2s_mma(acc0, ah0, bl0);
        s2s_mma(acc0, al0, bh0);
        s2s_mma(acc0, ah1, bh0 + 2);
        s2s_mma(acc0, ah1, bl0 + 2);
        s2s_mma(acc0, al1, bh0 + 2);
        s2s_mma(acc1, ah0, bh1);
        s2s_mma(acc1, ah0, bl1);
        s2s_mma(acc1, al0, bh1);
        s2s_mma(acc1, ah1, bh1 + 2);
        s2s_mma(acc1, ah1, bl1 + 2);
        s2s_mma(acc1, al1, bh1 + 2);
    }
}

__global__ __launch_bounds__(512, 1)
void s2s_lstm_persist(const float* __restrict__ eWhh0, const float* __restrict__ eWih1,
                      const float* __restrict__ eWhh1, const float* __restrict__ eb1,
                      const float* __restrict__ dWhh0, const float* __restrict__ dWih1,
                      const float* __restrict__ dWhh1, const float* __restrict__ db1) {
    extern __shared__ __nv_bfloat16 sm[];
    __nv_bfloat16* whi = sm;
    __nv_bfloat16* wlo = sm + 33024;
    __nv_bfloat16* ahi = sm + 66048;
    __nv_bfloat16* alo = sm + 82688;
    float* shG = (float*)(sm + 99328);
    const uint32_t aHiB = s2s_smem_u32(ahi), aLoB = s2s_smem_u32(alo);
    const uint32_t wHiB = s2s_smem_u32(whi), wLoB = s2s_smem_u32(wlo);

    const int tid = threadIdx.x, warp = tid >> 5, lane = tid & 31;
    const int kq = warp >> 2;
    const int mt = (warp >> 1) & 1, gp = warp & 1;
    const int g = lane >> 2, tq = lane & 3;
    const bool isA = blockIdx.x < NGRP;
    const int u0 = (isA ? blockIdx.x : blockIdx.x - NGRP) * 8;
    const int lrow = (tid & 255) >> 3, c4 = (tid & 7) * 4;
    const int WR = (lrow >> 3) * HID + u0 + (lrow & 7);
    const int eb = (tid & 255) >> 3, eu = tid & 7;
    const int U = u0 + eu;
    const int aoff  = (mt * 16 + (lane & 15)) * ABYTES + ((lane >> 4) << 4);
    const int boff0 = ((2 * gp) * 8 + (lane & 7)) * WBYTES + ((lane >> 3) << 4);
    const int boff1 = ((2 * gp + 1) * 8 + (lane & 7)) * WBYTES + ((lane >> 3) << 4);
    const bool low = (tid < 256);

    float creg = 0.0f;
    unsigned iter = 0;

    for (int phase = 0; phase < 2; phase++) {
        const float* Whh0 = phase ? dWhh0 : eWhh0;
        const float* Wih1 = phase ? dWih1 : eWih1;
        const float* Whh1 = phase ? dWhh1 : eWhh1;
        const float* bb1  = phase ? db1  : eb1;
        const float* xw   = s2s_xw_all + (phase ? (size_t)DECOFF * G4 : 0);
        const int steps   = phase ? T_STEPS : S_LEN;
        const int gbase   = phase ? S_LEN : 0;

        float bi1 = 0.f, bf1 = 0.f, bc1 = 0.f, bo1 = 0.f;
        if (!isA && low) {
            bi1 = __ldg(&bb1[U]); bf1 = __ldg(&bb1[HID + U]);
            bc1 = __ldg(&bb1[2 * HID + U]); bo1 = __ldg(&bb1[3 * HID + U]);
        }

        if (low) {
            if (isA) {
                for (int col = c4; col < HID; col += 32) {
                    float4 v = *(const float4*)&Whh0[(size_t)WR * HID + col];
                    const float* pv = (const float*)&v;
#pragma unroll
                    for (int i = 0; i < 4; i++)
                        s2s_split(pv[i], &whi[lrow * WS + col + i], &wlo[lrow * WS + col + i]);
                }
            } else {
                for (int col = c4; col < HID; col += 32) {
                    float4 v = *(const float4*)&Wih1[(size_t)WR * HID + col];
                    const float* pv = (const float*)&v;
#pragma unroll
                    for (int i = 0; i < 4; i++)
                        s2s_split(pv[i], &whi[lrow * WS + col + i], &wlo[lrow * WS + col + i]);
                    float4 v2 = *(const float4*)&Whh1[(size_t)WR * HID + col];
                    const float* pw = (const float*)&v2;
#pragma unroll
                    for (int i = 0; i < 4; i++)
                        s2s_split(pw[i], &whi[lrow * WS + 512 + col + i], &wlo[lrow * WS + 512 + col + i]);
                }
            }
        }
        __syncthreads();

        for (int j = 0; j <= steps; j++) {
            const bool act_me = isA ? (j < steps) : (j >= 1);
            if (act_me) {
                float acc0[4] = {0.f, 0.f, 0.f, 0.f};
                float acc1[4] = {0.f, 0.f, 0.f, 0.f};
                if (isA) {
                    const int gs = gbase + j;
                    const int rs = (gs + 3) & 3, ws = gs & 3;
                    const __nv_bfloat16* gHi = s2s_h0hi + (size_t)rs * BATCH * HID;
                    const __nv_bfloat16* gLo = s2s_h0lo + (size_t)rs * BATCH * HID;
#pragma unroll
                    for (int v = 0; v < 4; v++) {
                        int idx = tid + v * 512;
                        int row = idx >> 6, col = (idx & 63) * 8;
                        uint32_t d = (uint32_t)(row * ABYTES + col * 2);
                        s2s_cpasync(aHiB + d, gHi + (size_t)row * HID + col);
                        s2s_cpasync(aLoB + d, gLo + (size_t)row * HID + col);
                    }
                    CP_COMMIT();
                    float xg0 = 0.f, xg1 = 0.f, xg2 = 0.f, xg3 = 0.f;
                    if (low) {
                        const float* xwt = xw + (size_t)j * BATCH * G4 + (size_t)eb * G4;
                        xg0 = __ldg(&xwt[U]); xg1 = __ldg(&xwt[HID + U]);
                        xg2 = __ldg(&xwt[2 * HID + U]); xg3 = __ldg(&xwt[3 * HID + U]);
                    }
                    CP_WAIT0();
                    __syncthreads();
                    s2s_sweepG(aHiB, aLoB, wHiB, wLoB, aoff, boff0, boff1, kq * 4, acc0, acc1);
                    {
                        float* sg = shG + kq * 1024;
                        float* s0 = sg + (2 * gp) * 256;
                        float* s1 = sg + (2 * gp + 1) * 256;
                        s0[(mt * 16 + g) * 8 + 2 * tq]         = acc0[0];
                        s0[(mt * 16 + g) * 8 + 2 * tq + 1]     = acc0[1];
                        s0[(mt * 16 + g + 8) * 8 + 2 * tq]     = acc0[2];
                        s0[(mt * 16 + g + 8) * 8 + 2 * tq + 1] = acc0[3];
                        s1[(mt * 16 + g) * 8 + 2 * tq]         = acc1[0];
                        s1[(mt * 16 + g) * 8 + 2 * tq + 1]     = acc1[1];
                        s1[(mt * 16 + g + 8) * 8 + 2 * tq]     = acc1[2];
                        s1[(mt * 16 + g + 8) * 8 + 2 * tq + 1] = acc1[3];
                    }
                    __syncthreads();
                    if (low) {
                        const int o = eb * 8 + eu;
                        float gi = xg0, gf = xg1, gc = xg2, go = xg3;
#pragma unroll
                        for (int q = 0; q < 4; q++) {
                            gi += shG[q * 1024 + 0 * 256 + o];
                            gf += shG[q * 1024 + 1 * 256 + o];
                            gc += shG[q * 1024 + 2 * 256 + o];
                            go += shG[q * 1024 + 3 * 256 + o];
                        }
                        creg = s2s_sigm(gf) * creg + s2s_sigm(gi) * s2s_tanh(gc);
                        float h = s2s_sigm(go) * s2s_tanh(creg);
                        __nv_bfloat16 hh, hl;
                        s2s_split(h, &hh, &hl);
                        const size_t o1 = (size_t)ws * BATCH * HID + eb * HID + U;
                        const size_t o2 = (size_t)ws * BATCH * 1024 + eb * 1024 + U;
                        s2s_st16(&s2s_h0hi[o1], hh);  s2s_st16(&s2s_h0lo[o1], hl);
                        s2s_st16(&s2s_acthi[o2], hh); s2s_st16(&s2s_actlo[o2], hl);
                    }
                } else {
                    const int gs2 = gbase + j - 1;
                    const int sy = gs2 & 3, sh = (gs2 + 3) & 3, ws2 = gs2 & 3;
                    const __nv_bfloat16* yHi = s2s_acthi + (size_t)sy * BATCH * 1024;
                    const __nv_bfloat16* yLo = s2s_actlo + (size_t)sy * BATCH * 1024;
                    const __nv_bfloat16* hHi = s2s_acthi + (size_t)sh * BATCH * 1024;
                    const __nv_bfloat16* hLo = s2s_actlo + (size_t)sh * BATCH * 1024;
#pragma unroll
                    for (int v = 0; v < 4; v++) {
                        int idx = tid + v * 512;
                        int row = idx >> 6, col = (idx & 63) * 8;
                        uint32_t d = (uint32_t)(row * ABYTES + col * 2);
                        s2s_cpasync(aHiB + d, yHi + (size_t)row * 1024 + col);
                        s2s_cpasync(aLoB + d, yLo + (size_t)row * 1024 + col);
                    }
                    CP_COMMIT();
                    uint4 rh[4], rl[4];
#pragma unroll
                    for (int v = 0; v < 4; v++) {
                        int idx = tid + v * 512;
                        int row = idx >> 6, col = (idx & 63) * 8;
                        rh[v] = __ldcg((const uint4*)(hHi + (size_t)row * 1024 + 512 + col));
                        rl[v] = __ldcg((const uint4*)(hLo + (size_t)row * 1024 + 512 + col));
                    }
                    CP_WAIT0();
                    __syncthreads();
                    s2s_sweepG(aHiB, aLoB, wHiB, wLoB, aoff, boff0, boff1, kq * 4, acc0, acc1);
                    __syncthreads();
#pragma unroll
                    for (int v = 0; v < 4; v++) {
                        int idx = tid + v * 512;
                        int row = idx >> 6, col = (idx & 63) * 8;
                        uint32_t d = (uint32_t)(row * ABYTES + col * 2);
                        *(uint4*)((char*)ahi + d) = rh[v];
                        *(uint4*)((char*)alo + d) = rl[v];
                    }
                    __syncthreads();
                    s2s_sweepG(aHiB, aLoB, wHiB + 1024, wLoB + 1024, aoff, boff0, boff1, kq * 4, acc0, acc1);
                    {
                        float* sg = shG + kq * 1024;
                        float* s0 = sg + (2 * gp) * 256;
                        float* s1 = sg + (2 * gp + 1) * 256;
                        s0[(mt * 16 + g) * 8 + 2 * tq]         = acc0[0];
                        s0[(mt * 16 + g) * 8 + 2 * tq + 1]     = acc0[1];
                        s0[(mt * 16 + g + 8) * 8 + 2 * tq]     = acc0[2];
                        s0[(mt * 16 + g + 8) * 8 + 2 * tq + 1] = acc0[3];
                        s1[(mt * 16 + g) * 8 + 2 * tq]         = acc1[0];
                        s1[(mt * 16 + g) * 8 + 2 * tq + 1]     = acc1[1];
                        s1[(mt * 16 + g + 8) * 8 + 2 * tq]     = acc1[2];
                        s1[(mt * 16 + g + 8) * 8 + 2 * tq + 1] = acc1[3];
                    }
                    __syncthreads();
                    if (low) {
                        const int o = eb * 8 + eu;
                        float gi = bi1, gf = bf1, gc = bc1, go = bo1;
#pragma unroll
                        for (int q = 0; q < 4; q++) {
                            gi += shG[q * 1024 + 0 * 256 + o];
                            gf += shG[q * 1024 + 1 * 256 + o];
                            gc += shG[q * 1024 + 2 * 256 + o];
                            go += shG[q * 1024 + 3 * 256 + o];
                        }
                        creg = s2s_sigm(gf) * creg + s2s_sigm(gi) * s2s_tanh(gc);
                        float h = s2s_sigm(go) * s2s_tanh(creg);
                        __nv_bfloat16 hh, hl;
                        s2s_split(h, &hh, &hl);
                        const size_t o2 = (size_t)ws2 * BATCH * 1024 + eb * 1024 + 512 + U;
                        s2s_st16(&s2s_acthi[o2], hh); s2s_st16(&s2s_actlo[o2], hl);
                        if (phase == 1) {
                            const size_t od = (size_t)(j - 1) * BATCH * HID + eb * HID + U;
                            s2s_dy1hi[od] = hh;
                            s2s_dy1lo[od] = hl;
                        }
                    }
                }
            }
            iter++;
            __syncthreads();
            if (tid == 0) {
                __threadfence();
                unsigned* myB = isA ? &s2s_barA : &s2s_barB;
                atomicAdd(myB, 1u);
                while (*(volatile unsigned*)myB < iter * NGRP) { }
                if (isA) {
                    if (iter > 3)
                        while (*(volatile unsigned*)&s2s_barB < (iter - 3) * NGRP) { }
                } else {
                    while (*(volatile unsigned*)&s2s_barA < iter * NGRP) { }
                }
                __threadfence();
            }
            __syncthreads();
        }
    }
}

// ---------------- vocab projection: 3-stage pipeline, 1 sync per chunk -------
#define VTILE  8192
#define VSTAGE 32768
#define VSMEM  98304

__device__ __forceinline__ uint32_t s2s_vswz(int row, int c16) {
    return (uint32_t)(row * 64 + ((c16 ^ ((row >> 1) & 3)) << 4));
}

__global__ __launch_bounds__(256)
void s2s_vgemm(const __nv_bfloat16* __restrict__ Ahi, const __nv_bfloat16* __restrict__ Alo,
               const __nv_bfloat16* __restrict__ Bhi, const __nv_bfloat16* __restrict__ Blo,
               const float* __restrict__ bias, float* __restrict__ C, int Mvalid) {
    extern __shared__ char vsm[];
    const uint32_t sb = s2s_smem_u32(vsm);
    const int tid = threadIdx.x, wid = tid >> 5, lane = tid & 31;
    const int wm = wid >> 2, wn = wid & 3;
    const int g = lane >> 2, tq = lane & 3;
    const int bm = blockIdx.x * 128, bn = blockIdx.y * 128;

    const __nv_bfloat16* srcs[4] = {
        Ahi + (size_t)bm * HID, Alo + (size_t)bm * HID,
        Bhi + (size_t)bn * HID, Blo + (size_t)bn * HID };

    auto prefetch = [&](int ch, int st) {
#pragma unroll
        for (int t = 0; t < 4; t++) {
#pragma unroll
            for (int v = 0; v < 2; v++) {
                int idx = tid + v * 256;
                int row = idx >> 2, c16 = idx & 3;
                const __nv_bfloat16* gp = srcs[t] + (size_t)row * HID + ch * 32 + c16 * 8;
                s2s_cpasync(sb + st * VSTAGE + t * VTILE + s2s_vswz(row, c16), gp);
            }
        }
    };

    float acc[4][4][4];
#pragma unroll
    for (int i = 0; i < 4; i++)
#pragma unroll
        for (int j = 0; j < 4; j++)
#pragma unroll
            for (int k = 0; k < 4; k++) acc[i][j][k] = 0.0f;

    prefetch(0, 0);
    CP_COMMIT();
    prefetch(1, 1);
    CP_COMMIT();

    for (int ch = 0; ch < 16; ch++) {
        if (ch < 15) { CP_WAIT1(); } else { CP_WAIT0(); }
        __syncthreads();                 // data for ch ready; compute(ch-1) done everywhere
        if (ch + 2 < 16) { prefetch(ch + 2, (ch + 2) % 3); CP_COMMIT(); }

        const uint32_t base = sb + (ch % 3) * VSTAGE;
#pragma unroll
        for (int kk = 0; kk < 2; kk++) {
            uint32_t ah[4][4], al[4][4], bh2[2][4], bl2[2][4];
            const int arow = wm * 64 + (lane & 15);
            const int ac16 = kk * 2 + (lane >> 4);
#pragma unroll
            for (int mt = 0; mt < 4; mt++) {
                const uint32_t off = s2s_vswz(arow + mt * 16, ac16);
                s2s_ldsm4(ah[mt], base + off);
                s2s_ldsm4(al[mt], base + VTILE + off);
            }
            const int brow = wn * 32 + ((lane >> 4) << 3) + (lane & 7);
            const int bc16 = kk * 2 + ((lane >> 3) & 1);
#pragma unroll
            for (int nt2 = 0; nt2 < 2; nt2++) {
                const uint32_t off = s2s_vswz(brow + nt2 * 16, bc16);
                s2s_ldsm4(bh2[nt2], base + 2 * VTILE + off);
                s2s_ldsm4(bl2[nt2], base + 3 * VTILE + off);
            }
#pragma unroll
            for (int mt = 0; mt < 4; mt++)
#pragma unroll
                for (int nt = 0; nt < 4; nt++) {
                    const uint32_t* bh = &bh2[nt >> 1][(nt & 1) * 2];
                    const uint32_t* bl = &bl2[nt >> 1][(nt & 1) * 2];
                    s2s_mma(acc[mt][nt], ah[mt], bh);
                    s2s_mma(acc[mt][nt], ah[mt], bl);
                    s2s_mma(acc[mt][nt], al[mt], bh);
                }
        }
    }

#pragma unroll
    for (int mt = 0; mt < 4; mt++) {
#pragma unroll
        for (int nt = 0; nt < 4; nt++) {
            const int col = bn + wn * 32 + nt * 8 + 2 * tq;
            const float b0 = bias[col], b1 = bias[col + 1];
            const int r0 = bm + wm * 64 + mt * 16 + g;
            if (r0 < Mvalid) {
                float2 o = { acc[mt][nt][0] + b0, acc[mt][nt][1] + b1 };
                *(float2*)&C[(size_t)(r0 + BATCH) * VOCAB + col] = o;
            }
            if (r0 + 8 < Mvalid) {
                float2 o = { acc[mt][nt][2] + b0, acc[mt][nt][3] + b1 };
                *(float2*)&C[(size_t)(r0 + 8 + BATCH) * VOCAB + col] = o;
            }
        }
    }
}

static inline int s2s_grid(int n) { return (n + 255) / 256; }

extern "C" void kernel_launch(void* const* d_in, const int* in_sizes, int n_in,
                              void* d_out, int out_size) {
    (void)in_sizes; (void)n_in; (void)out_size;
    const int*   src      = (const int*)  d_in[0];
    const int*   trg      = (const int*)  d_in[1];
    const float* enc_emb  = (const float*)d_in[2];
    const float* enc_Wih0 = (const float*)d_in[3];
    const float* enc_Whh0 = (const float*)d_in[4];
    const float* enc_b0   = (const float*)d_in[5];
    const float* enc_Wih1 = (const float*)d_in[6];
    const float* enc_Whh1 = (const float*)d_in[7];
    const float* enc_b1   = (const float*)d_in[8];
    const float* dec_emb  = (const float*)d_in[9];
    const float* dec_Wih0 = (const float*)d_in[10];
    const float* dec_Whh0 = (const float*)d_in[11];
    const float* dec_b0   = (const float*)d_in[12];
    const float* dec_Wih1 = (const float*)d_in[13];
    const float* dec_Whh1 = (const float*)d_in[14];
    const float* dec_b1   = (const float*)d_in[15];
    const float* out_W    = (const float*)d_in[16];
    const float* out_b    = (const float*)d_in[17];
    float* out = (float*)d_out;

    __nv_bfloat16 *dy1hi, *dy1lo, *wvhi, *wvlo;
    cudaGetSymbolAddress((void**)&dy1hi, s2s_dy1hi);
    cudaGetSymbolAddress((void**)&dy1lo, s2s_dy1lo);
    cudaGetSymbolAddress((void**)&wvhi,  s2s_wvhi);
    cudaGetSymbolAddress((void**)&wvlo,  s2s_wvlo);

    cudaFuncSetAttribute(s2s_lstm_persist,
                         cudaFuncAttributeMaxDynamicSharedMemorySize, SMEM_BYTES);
    cudaFuncSetAttribute(s2s_vgemm,
                         cudaFuncAttributeMaxDynamicSharedMemorySize, VSMEM);

    // 0: init
    s2s_init_kernel<<<s2s_grid(BATCH * VOCAB), 256>>>(out);
    // 1: embeddings
    s2s_embed_all<<<s2s_grid((S_LEN + T_STEPS) * BATCH * EMB), 256>>>(src, trg, enc_emb, dec_emb);
    // 2: x-projections
    s2s_xproj<<<dim3(XROWS / GBM, G4 / GBN), 256>>>(enc_Wih0, enc_b0, dec_Wih0, dec_b0);
    // 3: recurrence (ncu lands here)
    s2s_lstm_persist<<<NBLK, 512, SMEM_BYTES>>>(
        enc_Whh0, enc_Wih1, enc_Whh1, enc_b1,
        dec_Whh0, dec_Wih1, dec_Whh1, dec_b1);
    // 4: split out_W
    s2s_split_mat<<<s2s_grid(VOCAB * HID), 256>>>(out_W, wvhi, wvlo, VOCAB * HID);
    // 5: vocab projection (3-stage, 1 sync/chunk)
    s2s_vgemm<<<dim3(MPAD / 128, VOCAB / 128), 256, VSMEM>>>(
        dy1hi, dy1lo, wvhi, wvlo, out_b, out, T_STEPS * BATCH);
}